// round 1
// baseline (speedup 1.0000x reference)
#include <cuda_runtime.h>
#include <math.h>

#define BATCHN 8
#define SEQL   2048
#define DM     1024
#define EDIM   2048
#define E2     4096
#define NST    16
#define RDIM   64
#define FDIM   96
#define MROWS  (BATCHN*SEQL)   // 16384

// ---------------- scratch (device globals; no runtime allocation) -----------
__device__ float g_h[(size_t)MROWS * DM];       //  64 MB
__device__ float g_xz[(size_t)MROWS * E2];      // 256 MB
__device__ float g_u[(size_t)MROWS * EDIM];     // 128 MB
__device__ float g_dbc[(size_t)MROWS * FDIM];   //   6 MB
__device__ float g_delta[(size_t)MROWS * EDIM]; // 128 MB
__device__ float g_y[(size_t)MROWS * EDIM];     // 128 MB

// ---------------- RMSNorm ----------------------------------------------------
__global__ __launch_bounds__(256) void rmsnorm_kernel(
    const float* __restrict__ x, const float* __restrict__ nw,
    float* __restrict__ h)
{
    __shared__ float red[8];
    __shared__ float s_scale;
    const int row = blockIdx.x;
    const int t = threadIdx.x;
    const float4 v = ((const float4*)(x + (size_t)row * DM))[t];
    float ss = v.x*v.x + v.y*v.y + v.z*v.z + v.w*v.w;
    #pragma unroll
    for (int o = 16; o > 0; o >>= 1) ss += __shfl_down_sync(0xffffffffu, ss, o);
    if ((t & 31) == 0) red[t >> 5] = ss;
    __syncthreads();
    if (t == 0) {
        float tot = 0.f;
        #pragma unroll
        for (int i = 0; i < 8; i++) tot += red[i];
        s_scale = rsqrtf(tot * (1.0f / DM) + 1e-5f);
    }
    __syncthreads();
    const float sc = s_scale;
    const float4 w = ((const float4*)nw)[t];
    float4 o;
    o.x = v.x * sc * w.x;
    o.y = v.y * sc * w.y;
    o.z = v.z * sc * w.z;
    o.w = v.w * sc * w.w;
    ((float4*)(h + (size_t)row * DM))[t] = o;
}

// ---------------- generic tiled fp32 GEMM: C[M,N] = A[M,K] * B[N,K]^T --------
// mode 0: plain   mode 1: +bias[n], softplus   mode 2: +resid[m*N+n]
__global__ __launch_bounds__(256) void gemm_nt(
    const float* __restrict__ A, int lda,
    const float* __restrict__ B,            // [N, Kd], ldb = Kd
    float* __restrict__ C,                  // [M, N]
    int M, int N, int Kd,
    int mode, const float* __restrict__ aux)
{
    __shared__ float As[16][128];
    __shared__ float Bs[16][128];
    const int tid = threadIdx.x;
    const int bm = blockIdx.y * 128;
    const int bn = blockIdx.x * 128;
    const int tx = tid & 15;
    const int ty = tid >> 4;

    float acc[8][8];
    #pragma unroll
    for (int i = 0; i < 8; i++)
        #pragma unroll
        for (int j = 0; j < 8; j++) acc[i][j] = 0.f;

    for (int kt = 0; kt < Kd; kt += 16) {
        #pragma unroll
        for (int i = 0; i < 2; ++i) {
            int idx = tid + i * 256;       // 0..511 float4 slot
            int row = idx >> 2;            // 0..127
            int c4  = idx & 3;
            float4 v = *(const float4*)(A + (size_t)(bm + row) * lda + kt + c4 * 4);
            As[c4*4+0][row] = v.x; As[c4*4+1][row] = v.y;
            As[c4*4+2][row] = v.z; As[c4*4+3][row] = v.w;
        }
        #pragma unroll
        for (int i = 0; i < 2; ++i) {
            int idx = tid + i * 256;
            int row = idx >> 2;
            int c4  = idx & 3;
            int n   = bn + row;
            float4 v = make_float4(0.f, 0.f, 0.f, 0.f);
            if (n < N) v = *(const float4*)(B + (size_t)n * Kd + kt + c4 * 4);
            Bs[c4*4+0][row] = v.x; Bs[c4*4+1][row] = v.y;
            Bs[c4*4+2][row] = v.z; Bs[c4*4+3][row] = v.w;
        }
        __syncthreads();
        #pragma unroll
        for (int k = 0; k < 16; ++k) {
            float4 a0 = *(const float4*)&As[k][ty * 8];
            float4 a1 = *(const float4*)&As[k][ty * 8 + 4];
            float4 b0 = *(const float4*)&Bs[k][tx * 8];
            float4 b1 = *(const float4*)&Bs[k][tx * 8 + 4];
            float a[8] = {a0.x, a0.y, a0.z, a0.w, a1.x, a1.y, a1.z, a1.w};
            float b[8] = {b0.x, b0.y, b0.z, b0.w, b1.x, b1.y, b1.z, b1.w};
            #pragma unroll
            for (int i = 0; i < 8; i++)
                #pragma unroll
                for (int j = 0; j < 8; j++)
                    acc[i][j] = fmaf(a[i], b[j], acc[i][j]);
        }
        __syncthreads();
    }

    #pragma unroll
    for (int i = 0; i < 8; i++) {
        const int m = bm + ty * 8 + i;
        const size_t roff = (size_t)m * N;
        #pragma unroll
        for (int j = 0; j < 8; j++) {
            const int n = bn + tx * 8 + j;
            if (n < N) {
                float v = acc[i][j];
                if (mode == 1) {
                    v += aux[n];
                    // softplus = max(v,0) + log1p(exp(-|v|))
                    v = fmaxf(v, 0.f) + log1pf(__expf(-fabsf(v)));
                } else if (mode == 2) {
                    v += aux[roff + n];
                }
                C[roff + n] = v;
            }
        }
    }
}

// ---------------- depthwise causal conv (K=4) + bias + SiLU ------------------
__global__ __launch_bounds__(256) void conv_silu_kernel(
    const float* __restrict__ xz, const float* __restrict__ w,
    const float* __restrict__ bias, float* __restrict__ u)
{
    const long long idx = (long long)blockIdx.x * blockDim.x + threadIdx.x;
    if (idx >= (long long)MROWS * EDIM) return;
    const int e  = (int)(idx & (EDIM - 1));
    const int ml = (int)(idx >> 11);       // b*L + l
    const int l  = ml & (SEQL - 1);
    float acc = bias[e];
    const float4 wv = *(const float4*)(w + e * 4);
    const float wk[4] = {wv.x, wv.y, wv.z, wv.w};
    #pragma unroll
    for (int k = 0; k < 4; k++) {
        const int ls = l - 3 + k;
        if (ls >= 0)
            acc = fmaf(xz[(size_t)(ml - 3 + k) * E2 + e], wk[k], acc);
    }
    const float s = 1.f / (1.f + __expf(-acc));
    u[(size_t)ml * EDIM + e] = acc * s;
}

// ---------------- selective scan: 4 threads per (b,e) chain ------------------
__global__ __launch_bounds__(256) void scan_kernel(
    const float* __restrict__ delta, const float* __restrict__ u,
    const float* __restrict__ dbc,   const float* __restrict__ xz,
    const float* __restrict__ A_log, const float* __restrict__ D_skip,
    float* __restrict__ y)
{
    const int g = blockIdx.x * blockDim.x + threadIdx.x; // 0..65535
    const int chain = g >> 2;
    const int tq = g & 3;
    const int b = chain >> 11;       // / EDIM
    const int e = chain & (EDIM - 1);

    float Av[4];
    #pragma unroll
    for (int i = 0; i < 4; i++)
        Av[i] = -__expf(A_log[e * NST + tq * 4 + i]);
    const float Dv = D_skip[e];

    float hs0 = 0.f, hs1 = 0.f, hs2 = 0.f, hs3 = 0.f;
    const size_t base = (size_t)b * SEQL;

    for (int l = 0; l < SEQL; ++l) {
        const size_t r = base + l;
        const float d  = delta[r * EDIM + e];
        const float uu = u[r * EDIM + e];
        const float zz = xz[r * E2 + EDIM + e];
        const float4 Bv = *(const float4*)(dbc + r * FDIM + RDIM + tq * 4);
        const float4 Cv = *(const float4*)(dbc + r * FDIM + RDIM + NST + tq * 4);
        const float du = d * uu;

        hs0 = fmaf(hs0, __expf(d * Av[0]), du * Bv.x);
        hs1 = fmaf(hs1, __expf(d * Av[1]), du * Bv.y);
        hs2 = fmaf(hs2, __expf(d * Av[2]), du * Bv.z);
        hs3 = fmaf(hs3, __expf(d * Av[3]), du * Bv.w);

        float yp = hs0 * Cv.x + hs1 * Cv.y + hs2 * Cv.z + hs3 * Cv.w;
        yp += __shfl_xor_sync(0xffffffffu, yp, 1);
        yp += __shfl_xor_sync(0xffffffffu, yp, 2);

        if (tq == 0) {
            const float sg = 1.f / (1.f + __expf(-zz));
            y[r * EDIM + e] = (yp + uu * Dv) * (zz * sg);
        }
    }
}

// ---------------- launch ------------------------------------------------------
extern "C" void kernel_launch(void* const* d_in, const int* in_sizes, int n_in,
                              void* d_out, int out_size)
{
    const float* x          = (const float*)d_in[0];
    const float* norm_w     = (const float*)d_in[1];
    const float* in_proj_w  = (const float*)d_in[2];
    const float* conv_w     = (const float*)d_in[3];
    const float* conv_b     = (const float*)d_in[4];
    const float* x_proj_w   = (const float*)d_in[5];
    const float* dt_proj_w  = (const float*)d_in[6];
    const float* dt_proj_b  = (const float*)d_in[7];
    const float* A_log      = (const float*)d_in[8];
    const float* D_skip     = (const float*)d_in[9];
    const float* out_proj_w = (const float*)d_in[10];
    float* out = (float*)d_out;

    float *ph, *pxz, *pu, *pdbc, *pdelta, *py;
    cudaGetSymbolAddress((void**)&ph,     g_h);
    cudaGetSymbolAddress((void**)&pxz,    g_xz);
    cudaGetSymbolAddress((void**)&pu,     g_u);
    cudaGetSymbolAddress((void**)&pdbc,   g_dbc);
    cudaGetSymbolAddress((void**)&pdelta, g_delta);
    cudaGetSymbolAddress((void**)&py,     g_y);

    // 1. RMSNorm
    rmsnorm_kernel<<<MROWS, 256>>>(x, norm_w, ph);

    // 2. xz = h @ in_proj_w^T   [16384, 4096]
    {
        dim3 grid(E2 / 128, MROWS / 128);
        gemm_nt<<<grid, 256>>>(ph, DM, in_proj_w, pxz, MROWS, E2, DM, 0, nullptr);
    }

    // 3. depthwise conv + SiLU -> u [16384, 2048]
    {
        long long tot = (long long)MROWS * EDIM;
        conv_silu_kernel<<<(unsigned)((tot + 255) / 256), 256>>>(pxz, conv_w, conv_b, pu);
    }

    // 4. dbc = u @ x_proj_w^T  [16384, 96]
    {
        dim3 grid((FDIM + 127) / 128, MROWS / 128);
        gemm_nt<<<grid, 256>>>(pu, EDIM, x_proj_w, pdbc, MROWS, FDIM, EDIM, 0, nullptr);
    }

    // 5. delta = softplus(dbc[:, :64] @ dt_proj_w^T + b)  [16384, 2048]
    {
        dim3 grid(EDIM / 128, MROWS / 128);
        gemm_nt<<<grid, 256>>>(pdbc, FDIM, dt_proj_w, pdelta, MROWS, EDIM, RDIM, 1, dt_proj_b);
    }

    // 6. selective scan (fused D-skip + SiLU(z) gate) -> y [16384, 2048]
    scan_kernel<<<(MROWS * 4) / 256, 256>>>(pdelta, pu, pdbc, pxz, A_log, D_skip, py);

    // 7. out = y @ out_proj_w^T + x   [16384, 1024]
    {
        dim3 grid(DM / 128, MROWS / 128);
        gemm_nt<<<grid, 256>>>(py, EDIM, out_proj_w, out, MROWS, DM, EDIM, 2, x);
    }
}

// round 3
// speedup vs baseline: 1.7910x; 1.7910x over previous
#include <cuda_runtime.h>
#include <math.h>
#include <stdint.h>

#define BATCHN 8
#define SEQL   2048
#define DM     1024
#define EDIM   2048
#define E2     4096
#define NST    16
#define RDIM   64
#define FDIM   96
#define MROWS  (BATCHN*SEQL)   // 16384

// ---------------- scratch (device globals; no runtime allocation) -----------
__device__ float g_h[(size_t)MROWS * DM];
__device__ float g_xz[(size_t)MROWS * E2];
__device__ float g_u[(size_t)MROWS * EDIM];
__device__ float g_dbc[(size_t)MROWS * FDIM];
__device__ float g_delta[(size_t)MROWS * EDIM];
__device__ float g_y[(size_t)MROWS * EDIM];

// ====================== tf32 mma.sync GEMM ===================================
// C[M,N] = A[M,K] * B[N,K]^T    (both K-major fp32)
// mode 0: plain   mode 1: +bias[n], softplus   mode 2: +resid[m*N+n]
// SMEM: 2 buffers x (A 128x32 + B 128x32) fp32, row stride 36 floats (pad).
#define TSTR 36
#define TILE_FLOATS (128 * TSTR)              // 4608 per matrix
#define BUF_FLOATS  (2 * TILE_FLOATS)         // 9216 per buffer (A+B)
#define GEMM_SMEM_BYTES (2 * BUF_FLOATS * 4)  // 73728

__device__ __forceinline__ uint32_t f2tf32(float f) {
    uint32_t r;
    asm("cvt.rna.tf32.f32 %0, %1;" : "=r"(r) : "f"(f));
    return r;
}

__device__ __forceinline__ void mma_tf32(
    float* c, uint32_t a0, uint32_t a1, uint32_t a2, uint32_t a3,
    uint32_t b0, uint32_t b1)
{
    asm volatile(
        "mma.sync.aligned.m16n8k8.row.col.f32.tf32.tf32.f32 "
        "{%0,%1,%2,%3}, {%4,%5,%6,%7}, {%8,%9}, {%0,%1,%2,%3};"
        : "+f"(c[0]), "+f"(c[1]), "+f"(c[2]), "+f"(c[3])
        : "r"(a0), "r"(a1), "r"(a2), "r"(a3), "r"(b0), "r"(b1));
}

__global__ __launch_bounds__(256) void gemm_mma(
    const float* __restrict__ A, int lda,
    const float* __restrict__ B,           // [N, Kd] row-major
    float* __restrict__ C,                 // [M, N]
    int M, int N, int Kd,
    int mode, const float* __restrict__ aux)
{
    extern __shared__ float smf[];
    const int tid  = threadIdx.x;
    const int lane = tid & 31;
    const int wid  = tid >> 5;
    const int wm   = wid >> 1;             // 0..3  (m quadrant, 32 rows)
    const int wn   = wid & 1;              // 0..1  (n half, 64 cols)
    const int g    = lane >> 2;            // 0..7
    const int t4   = lane & 3;             // 0..3
    const int bm   = blockIdx.y * 128;
    const int bn   = blockIdx.x * 128;

    // per-thread fill coordinates (4 float4 per matrix per tile)
    int f_row[4], f_c4[4];
    #pragma unroll
    for (int i = 0; i < 4; ++i) {
        const int idx = tid + i * 256;     // 0..1023
        f_row[i] = idx >> 3;
        f_c4[i]  = idx & 7;
    }

    float4 ra[4], rb[4];
    const int KT = Kd >> 5;

    // ---- prologue: tile 0 ----
    {
        #pragma unroll
        for (int i = 0; i < 4; ++i) {
            ra[i] = *(const float4*)(A + (size_t)(bm + f_row[i]) * lda + f_c4[i] * 4);
            const int n = bn + f_row[i];
            rb[i] = (n < N) ? *(const float4*)(B + (size_t)n * Kd + f_c4[i] * 4)
                            : make_float4(0.f, 0.f, 0.f, 0.f);
        }
        float* as = smf;
        float* bs = smf + TILE_FLOATS;
        #pragma unroll
        for (int i = 0; i < 4; ++i) {
            float4 av, bv;
            av.x = __uint_as_float(f2tf32(ra[i].x));
            av.y = __uint_as_float(f2tf32(ra[i].y));
            av.z = __uint_as_float(f2tf32(ra[i].z));
            av.w = __uint_as_float(f2tf32(ra[i].w));
            bv.x = __uint_as_float(f2tf32(rb[i].x));
            bv.y = __uint_as_float(f2tf32(rb[i].y));
            bv.z = __uint_as_float(f2tf32(rb[i].z));
            bv.w = __uint_as_float(f2tf32(rb[i].w));
            *(float4*)(as + f_row[i] * TSTR + f_c4[i] * 4) = av;
            *(float4*)(bs + f_row[i] * TSTR + f_c4[i] * 4) = bv;
        }
    }
    __syncthreads();

    float acc[2][8][4];
    #pragma unroll
    for (int ms = 0; ms < 2; ++ms)
        #pragma unroll
        for (int ns = 0; ns < 8; ++ns)
            #pragma unroll
            for (int j = 0; j < 4; ++j) acc[ms][ns][j] = 0.f;

    for (int kt = 0; kt < KT; ++kt) {
        const int p = kt & 1;
        // issue global loads for next tile early
        if (kt + 1 < KT) {
            const int kbase = (kt + 1) << 5;
            #pragma unroll
            for (int i = 0; i < 4; ++i) {
                ra[i] = *(const float4*)(A + (size_t)(bm + f_row[i]) * lda + kbase + f_c4[i] * 4);
                const int n = bn + f_row[i];
                rb[i] = (n < N) ? *(const float4*)(B + (size_t)n * Kd + kbase + f_c4[i] * 4)
                                : make_float4(0.f, 0.f, 0.f, 0.f);
            }
        }
        // compute from smem buffer p
        {
            const float* as = smf + p * BUF_FLOATS + (wm * 32) * TSTR;
            const float* bs = smf + p * BUF_FLOATS + TILE_FLOATS + (wn * 64) * TSTR;
            #pragma unroll
            for (int ks = 0; ks < 4; ++ks) {
                const int k8 = ks * 8;
                uint32_t a[2][4];
                #pragma unroll
                for (int ms = 0; ms < 2; ++ms) {
                    const float* ap = as + (ms * 16) * TSTR;
                    a[ms][0] = __float_as_uint(ap[(g    ) * TSTR + k8 + t4]);
                    a[ms][1] = __float_as_uint(ap[(g + 8) * TSTR + k8 + t4]);
                    a[ms][2] = __float_as_uint(ap[(g    ) * TSTR + k8 + t4 + 4]);
                    a[ms][3] = __float_as_uint(ap[(g + 8) * TSTR + k8 + t4 + 4]);
                }
                #pragma unroll
                for (int ns = 0; ns < 8; ++ns) {
                    const float* bp = bs + (ns * 8) * TSTR;
                    const uint32_t b0 = __float_as_uint(bp[g * TSTR + k8 + t4]);
                    const uint32_t b1 = __float_as_uint(bp[g * TSTR + k8 + t4 + 4]);
                    mma_tf32(acc[0][ns], a[0][0], a[0][1], a[0][2], a[0][3], b0, b1);
                    mma_tf32(acc[1][ns], a[1][0], a[1][1], a[1][2], a[1][3], b0, b1);
                }
            }
        }
        if (kt + 1 < KT) {
            __syncthreads();
            float* as = smf + (p ^ 1) * BUF_FLOATS;
            float* bs = as + TILE_FLOATS;
            #pragma unroll
            for (int i = 0; i < 4; ++i) {
                float4 av, bv;
                av.x = __uint_as_float(f2tf32(ra[i].x));
                av.y = __uint_as_float(f2tf32(ra[i].y));
                av.z = __uint_as_float(f2tf32(ra[i].z));
                av.w = __uint_as_float(f2tf32(ra[i].w));
                bv.x = __uint_as_float(f2tf32(rb[i].x));
                bv.y = __uint_as_float(f2tf32(rb[i].y));
                bv.z = __uint_as_float(f2tf32(rb[i].z));
                bv.w = __uint_as_float(f2tf32(rb[i].w));
                *(float4*)(as + f_row[i] * TSTR + f_c4[i] * 4) = av;
                *(float4*)(bs + f_row[i] * TSTR + f_c4[i] * 4) = bv;
            }
            __syncthreads();
        }
    }

    // ---- epilogue ----
    #pragma unroll
    for (int ms = 0; ms < 2; ++ms) {
        const int row0 = bm + wm * 32 + ms * 16 + g;
        #pragma unroll
        for (int ns = 0; ns < 8; ++ns) {
            const int col = bn + wn * 64 + ns * 8 + 2 * t4;
            if (col < N) {
                float v0 = acc[ms][ns][0], v1 = acc[ms][ns][1];
                float v2 = acc[ms][ns][2], v3 = acc[ms][ns][3];
                const size_t r0 = (size_t)row0 * N;
                const size_t r1 = (size_t)(row0 + 8) * N;
                if (mode == 1) {
                    const float b0 = aux[col], b1 = aux[col + 1];
                    v0 += b0; v1 += b1; v2 += b0; v3 += b1;
                    v0 = fmaxf(v0, 0.f) + log1pf(__expf(-fabsf(v0)));
                    v1 = fmaxf(v1, 0.f) + log1pf(__expf(-fabsf(v1)));
                    v2 = fmaxf(v2, 0.f) + log1pf(__expf(-fabsf(v2)));
                    v3 = fmaxf(v3, 0.f) + log1pf(__expf(-fabsf(v3)));
                } else if (mode == 2) {
                    const float2 x0 = *(const float2*)(aux + r0 + col);
                    const float2 x1 = *(const float2*)(aux + r1 + col);
                    v0 += x0.x; v1 += x0.y; v2 += x1.x; v3 += x1.y;
                }
                *(float2*)(C + r0 + col) = make_float2(v0, v1);
                *(float2*)(C + r1 + col) = make_float2(v2, v3);
            }
        }
    }
}

// ---------------- RMSNorm ----------------------------------------------------
__global__ __launch_bounds__(256) void rmsnorm_kernel(
    const float* __restrict__ x, const float* __restrict__ nw,
    float* __restrict__ h)
{
    __shared__ float red[8];
    __shared__ float s_scale;
    const int row = blockIdx.x;
    const int t = threadIdx.x;
    const float4 v = ((const float4*)(x + (size_t)row * DM))[t];
    float ss = v.x*v.x + v.y*v.y + v.z*v.z + v.w*v.w;
    #pragma unroll
    for (int o = 16; o > 0; o >>= 1) ss += __shfl_down_sync(0xffffffffu, ss, o);
    if ((t & 31) == 0) red[t >> 5] = ss;
    __syncthreads();
    if (t == 0) {
        float tot = 0.f;
        #pragma unroll
        for (int i = 0; i < 8; i++) tot += red[i];
        s_scale = rsqrtf(tot * (1.0f / DM) + 1e-5f);
    }
    __syncthreads();
    const float sc = s_scale;
    const float4 w = ((const float4*)nw)[t];
    float4 o;
    o.x = v.x * sc * w.x;
    o.y = v.y * sc * w.y;
    o.z = v.z * sc * w.z;
    o.w = v.w * sc * w.w;
    ((float4*)(h + (size_t)row * DM))[t] = o;
}

// ---------------- depthwise causal conv (K=4) + bias + SiLU ------------------
__global__ __launch_bounds__(256) void conv_silu_kernel(
    const float* __restrict__ xz, const float* __restrict__ w,
    const float* __restrict__ bias, float* __restrict__ u)
{
    const long long idx = (long long)blockIdx.x * blockDim.x + threadIdx.x;
    if (idx >= (long long)MROWS * EDIM) return;
    const int e  = (int)(idx & (EDIM - 1));
    const int ml = (int)(idx >> 11);
    const int l  = ml & (SEQL - 1);
    float acc = bias[e];
    const float4 wv = *(const float4*)(w + e * 4);
    const float wk[4] = {wv.x, wv.y, wv.z, wv.w};
    #pragma unroll
    for (int k = 0; k < 4; k++) {
        const int ls = l - 3 + k;
        if (ls >= 0)
            acc = fmaf(xz[(size_t)(ml - 3 + k) * E2 + e], wk[k], acc);
    }
    const float s = 1.f / (1.f + __expf(-acc));
    u[(size_t)ml * EDIM + e] = acc * s;
}

// ---------------- selective scan: 4 threads per (b,e) chain ------------------
__global__ __launch_bounds__(256) void scan_kernel(
    const float* __restrict__ delta, const float* __restrict__ u,
    const float* __restrict__ dbc,   const float* __restrict__ xz,
    const float* __restrict__ A_log, const float* __restrict__ D_skip,
    float* __restrict__ y)
{
    const int g = blockIdx.x * blockDim.x + threadIdx.x;
    const int chain = g >> 2;
    const int tq = g & 3;
    const int b = chain >> 11;
    const int e = chain & (EDIM - 1);

    float Av[4];
    #pragma unroll
    for (int i = 0; i < 4; i++)
        Av[i] = -__expf(A_log[e * NST + tq * 4 + i]);
    const float Dv = D_skip[e];

    float hs0 = 0.f, hs1 = 0.f, hs2 = 0.f, hs3 = 0.f;
    const size_t base = (size_t)b * SEQL;

    for (int l = 0; l < SEQL; ++l) {
        const size_t r = base + l;
        const float d  = delta[r * EDIM + e];
        const float uu = u[r * EDIM + e];
        const float zz = xz[r * E2 + EDIM + e];
        const float4 Bv = *(const float4*)(dbc + r * FDIM + RDIM + tq * 4);
        const float4 Cv = *(const float4*)(dbc + r * FDIM + RDIM + NST + tq * 4);
        const float du = d * uu;

        hs0 = fmaf(hs0, __expf(d * Av[0]), du * Bv.x);
        hs1 = fmaf(hs1, __expf(d * Av[1]), du * Bv.y);
        hs2 = fmaf(hs2, __expf(d * Av[2]), du * Bv.z);
        hs3 = fmaf(hs3, __expf(d * Av[3]), du * Bv.w);

        float yp = hs0 * Cv.x + hs1 * Cv.y + hs2 * Cv.z + hs3 * Cv.w;
        yp += __shfl_xor_sync(0xffffffffu, yp, 1);
        yp += __shfl_xor_sync(0xffffffffu, yp, 2);

        if (tq == 0) {
            const float sg = 1.f / (1.f + __expf(-zz));
            y[r * EDIM + e] = (yp + uu * Dv) * (zz * sg);
        }
    }
}

// ---------------- launch ------------------------------------------------------
extern "C" void kernel_launch(void* const* d_in, const int* in_sizes, int n_in,
                              void* d_out, int out_size)
{
    const float* x          = (const float*)d_in[0];
    const float* norm_w     = (const float*)d_in[1];
    const float* in_proj_w  = (const float*)d_in[2];
    const float* conv_w     = (const float*)d_in[3];
    const float* conv_b     = (const float*)d_in[4];
    const float* x_proj_w   = (const float*)d_in[5];
    const float* dt_proj_w  = (const float*)d_in[6];
    const float* dt_proj_b  = (const float*)d_in[7];
    const float* A_log      = (const float*)d_in[8];
    const float* D_skip     = (const float*)d_in[9];
    const float* out_proj_w = (const float*)d_in[10];
    float* out = (float*)d_out;

    float *ph, *pxz, *pu, *pdbc, *pdelta, *py;
    cudaGetSymbolAddress((void**)&ph,     g_h);
    cudaGetSymbolAddress((void**)&pxz,    g_xz);
    cudaGetSymbolAddress((void**)&pu,     g_u);
    cudaGetSymbolAddress((void**)&pdbc,   g_dbc);
    cudaGetSymbolAddress((void**)&pdelta, g_delta);
    cudaGetSymbolAddress((void**)&py,     g_y);

    cudaFuncSetAttribute(gemm_mma, cudaFuncAttributeMaxDynamicSharedMemorySize,
                         GEMM_SMEM_BYTES);

    // 1. RMSNorm
    rmsnorm_kernel<<<MROWS, 256>>>(x, norm_w, ph);

    // 2. xz = h @ in_proj_w^T   [16384, 4096]
    {
        dim3 grid(E2 / 128, MROWS / 128);
        gemm_mma<<<grid, 256, GEMM_SMEM_BYTES>>>(ph, DM, in_proj_w, pxz,
                                                 MROWS, E2, DM, 0, nullptr);
    }

    // 3. depthwise conv + SiLU -> u [16384, 2048]
    {
        long long tot = (long long)MROWS * EDIM;
        conv_silu_kernel<<<(unsigned)((tot + 255) / 256), 256>>>(pxz, conv_w, conv_b, pu);
    }

    // 4. dbc = u @ x_proj_w^T  [16384, 96]
    {
        dim3 grid(1, MROWS / 128);
        gemm_mma<<<grid, 256, GEMM_SMEM_BYTES>>>(pu, EDIM, x_proj_w, pdbc,
                                                 MROWS, FDIM, EDIM, 0, nullptr);
    }

    // 5. delta = softplus(dbc[:, :64] @ dt_proj_w^T + b)  [16384, 2048]
    {
        dim3 grid(EDIM / 128, MROWS / 128);
        gemm_mma<<<grid, 256, GEMM_SMEM_BYTES>>>(pdbc, FDIM, dt_proj_w, pdelta,
                                                 MROWS, EDIM, RDIM, 1, dt_proj_b);
    }

    // 6. selective scan (fused D-skip + SiLU(z) gate) -> y [16384, 2048]
    scan_kernel<<<(MROWS * 4) / 256, 256>>>(pdelta, pu, pdbc, pxz, A_log, D_skip, py);

    // 7. out = y @ out_proj_w^T + x   [16384, 1024]
    {
        dim3 grid(DM / 128, MROWS / 128);
        gemm_mma<<<grid, 256, GEMM_SMEM_BYTES>>>(py, EDIM, out_proj_w, out,
                                                 MROWS, DM, EDIM, 2, x);
    }
}

// round 4
// speedup vs baseline: 2.0404x; 1.1392x over previous
#include <cuda_runtime.h>
#include <math.h>
#include <stdint.h>

#define BATCHN 8
#define SEQL   2048
#define DM     1024
#define EDIM   2048
#define E2     4096
#define NST    16
#define RDIM   64
#define FDIM   96
#define MROWS  (BATCHN*SEQL)   // 16384

// ---------------- scratch (device globals; no runtime allocation) -----------
__device__ float g_h[(size_t)MROWS * DM];
__device__ float g_xz[(size_t)MROWS * E2];
__device__ float g_u[(size_t)MROWS * EDIM];
__device__ float g_dbc[(size_t)MROWS * FDIM];
__device__ float g_delta[(size_t)MROWS * EDIM];
__device__ float g_y[(size_t)MROWS * EDIM];
// pre-rounded (tf32) weights
__device__ float g_w_in [(size_t)E2 * DM];
__device__ float g_w_x  [(size_t)FDIM * EDIM];
__device__ float g_w_dt [(size_t)EDIM * RDIM];
__device__ float g_w_out[(size_t)DM * EDIM];

__device__ __forceinline__ float f2tf32f(float f) {
    uint32_t r;
    asm("cvt.rna.tf32.f32 %0, %1;" : "=r"(r) : "f"(f));
    return __uint_as_float(r);
}

// ---------------- tf32 rounding pre-pass -------------------------------------
__global__ __launch_bounds__(256) void round_tf32_k(
    const float* __restrict__ in, float* __restrict__ out, int n4)
{
    const int i = blockIdx.x * blockDim.x + threadIdx.x;
    if (i < n4) {
        float4 v = ((const float4*)in)[i];
        v.x = f2tf32f(v.x); v.y = f2tf32f(v.y);
        v.z = f2tf32f(v.z); v.w = f2tf32f(v.w);
        ((float4*)out)[i] = v;
    }
}

// ====================== tf32 mma.sync GEMM (cp.async) ========================
// C[M,N] = A[M,K] * B[N,K]^T ; A,B already tf32-rounded in gmem.
// mode 0: plain   mode 1: +bias[n], softplus   mode 2: +resid[m*N+n]
// round_out: store with cvt.rna.tf32
#define TSTR 36
#define TILE_F (128 * TSTR)                  // 4608 floats / matrix / stage
#define STAGE_F (2 * TILE_F)                 // 9216
#define GEMM_SMEM_BYTES (2 * STAGE_F * 4)    // 73728 (2 stages)

__device__ __forceinline__ void cpa16(uint32_t dst, const void* src, bool pred) {
    const int sz = pred ? 16 : 0;
    asm volatile("cp.async.cg.shared.global [%0], [%1], 16, %2;"
                 :: "r"(dst), "l"(src), "r"(sz));
}
#define CP_COMMIT() asm volatile("cp.async.commit_group;" ::: "memory")
#define CP_WAIT1()  asm volatile("cp.async.wait_group 1;" ::: "memory")

__device__ __forceinline__ void mma_tf32(
    float* c, uint32_t a0, uint32_t a1, uint32_t a2, uint32_t a3,
    uint32_t b0, uint32_t b1)
{
    asm volatile(
        "mma.sync.aligned.m16n8k8.row.col.f32.tf32.tf32.f32 "
        "{%0,%1,%2,%3}, {%4,%5,%6,%7}, {%8,%9}, {%0,%1,%2,%3};"
        : "+f"(c[0]), "+f"(c[1]), "+f"(c[2]), "+f"(c[3])
        : "r"(a0), "r"(a1), "r"(a2), "r"(a3), "r"(b0), "r"(b1));
}

__device__ __forceinline__ uint32_t smem_to_u32(const void* p) {
    uint32_t a;
    asm("{ .reg .u64 t; cvta.to.shared.u64 t, %1; cvt.u32.u64 %0, t; }" : "=r"(a) : "l"(p));
    return a;
}

__global__ __launch_bounds__(128, 2) void gemm_mma4(
    const float* __restrict__ A, int lda,
    const float* __restrict__ B,           // [N, Kd] row-major
    float* __restrict__ C,                 // [M, N]
    int M, int N, int Kd,
    int mode, const float* __restrict__ aux, int round_out)
{
    extern __shared__ float smf[];
    const uint32_t smem_u = smem_to_u32(smf);
    const int tid  = threadIdx.x;
    const int lane = tid & 31;
    const int wid  = tid >> 5;             // 0..3
    const int wm   = wid >> 1;             // 0..1  (64-row half)
    const int wn   = wid & 1;              // 0..1  (64-col half)
    const int g    = lane >> 2;            // 0..7
    const int t4   = lane & 3;             // 0..3
    const int bm   = blockIdx.y * 128;
    const int bn   = blockIdx.x * 128;
    const int KT   = Kd >> 5;

    // per-thread copy slots (8 float4 per matrix per tile)
    int f_row[8], f_c4[8];
    #pragma unroll
    for (int i = 0; i < 8; ++i) {
        const int slot = tid + i * 128;    // 0..1023
        f_row[i] = slot >> 3;
        f_c4[i]  = slot & 7;
    }

    // prologue: issue tile 0
    {
        const uint32_t ab = smem_u;
        const uint32_t bb = smem_u + TILE_F * 4;
        #pragma unroll
        for (int i = 0; i < 8; ++i) {
            const uint32_t off = f_row[i] * (TSTR * 4) + f_c4[i] * 16;
            cpa16(ab + off, A + (size_t)(bm + f_row[i]) * lda + f_c4[i] * 4, true);
            cpa16(bb + off, B + (size_t)(bn + f_row[i]) * Kd + f_c4[i] * 4,
                  bn + f_row[i] < N);
        }
        CP_COMMIT();
    }

    float acc[4][8][4];
    #pragma unroll
    for (int m = 0; m < 4; ++m)
        #pragma unroll
        for (int n = 0; n < 8; ++n)
            #pragma unroll
            for (int j = 0; j < 4; ++j) acc[m][n][j] = 0.f;

    for (int kt = 0; kt < KT; ++kt) {
        // issue next tile into the other stage
        if (kt + 1 < KT) {
            const int s = (kt + 1) & 1;
            const int kbase = (kt + 1) << 5;
            const uint32_t ab = smem_u + s * (STAGE_F * 4);
            const uint32_t bb = ab + TILE_F * 4;
            #pragma unroll
            for (int i = 0; i < 8; ++i) {
                const uint32_t off = f_row[i] * (TSTR * 4) + f_c4[i] * 16;
                cpa16(ab + off, A + (size_t)(bm + f_row[i]) * lda + kbase + f_c4[i] * 4, true);
                cpa16(bb + off, B + (size_t)(bn + f_row[i]) * Kd + kbase + f_c4[i] * 4,
                      bn + f_row[i] < N);
            }
        }
        CP_COMMIT();
        CP_WAIT1();                // tile kt resident
        __syncthreads();

        const float* as = smf + (kt & 1) * STAGE_F + (wm * 64) * TSTR;
        const float* bs = smf + (kt & 1) * STAGE_F + TILE_F + (wn * 64) * TSTR;
        #pragma unroll
        for (int ks = 0; ks < 4; ++ks) {
            const int k8 = ks * 8;
            uint32_t a[4][4];
            #pragma unroll
            for (int m = 0; m < 4; ++m) {
                const float* ap = as + (m * 16) * TSTR;
                a[m][0] = __float_as_uint(ap[(g    ) * TSTR + k8 + t4]);
                a[m][1] = __float_as_uint(ap[(g + 8) * TSTR + k8 + t4]);
                a[m][2] = __float_as_uint(ap[(g    ) * TSTR + k8 + t4 + 4]);
                a[m][3] = __float_as_uint(ap[(g + 8) * TSTR + k8 + t4 + 4]);
            }
            uint32_t b[8][2];
            #pragma unroll
            for (int n = 0; n < 8; ++n) {
                const float* bp = bs + (n * 8) * TSTR;
                b[n][0] = __float_as_uint(bp[g * TSTR + k8 + t4]);
                b[n][1] = __float_as_uint(bp[g * TSTR + k8 + t4 + 4]);
            }
            #pragma unroll
            for (int m = 0; m < 4; ++m)
                #pragma unroll
                for (int n = 0; n < 8; ++n)
                    mma_tf32(acc[m][n], a[m][0], a[m][1], a[m][2], a[m][3],
                             b[n][0], b[n][1]);
        }
        __syncthreads();
    }

    // ---- epilogue ----
    #pragma unroll
    for (int m = 0; m < 4; ++m) {
        const int row0 = bm + wm * 64 + m * 16 + g;
        const size_t r0 = (size_t)row0 * N;
        const size_t r1 = (size_t)(row0 + 8) * N;
        #pragma unroll
        for (int n = 0; n < 8; ++n) {
            const int col = bn + wn * 64 + n * 8 + 2 * t4;
            if (col < N) {
                float v0 = acc[m][n][0], v1 = acc[m][n][1];
                float v2 = acc[m][n][2], v3 = acc[m][n][3];
                if (mode == 1) {
                    const float b0 = aux[col], b1 = aux[col + 1];
                    v0 += b0; v1 += b1; v2 += b0; v3 += b1;
                    v0 = fmaxf(v0, 0.f) + log1pf(__expf(-fabsf(v0)));
                    v1 = fmaxf(v1, 0.f) + log1pf(__expf(-fabsf(v1)));
                    v2 = fmaxf(v2, 0.f) + log1pf(__expf(-fabsf(v2)));
                    v3 = fmaxf(v3, 0.f) + log1pf(__expf(-fabsf(v3)));
                } else if (mode == 2) {
                    const float2 x0 = *(const float2*)(aux + r0 + col);
                    const float2 x1 = *(const float2*)(aux + r1 + col);
                    v0 += x0.x; v1 += x0.y; v2 += x1.x; v3 += x1.y;
                }
                if (round_out) {
                    v0 = f2tf32f(v0); v1 = f2tf32f(v1);
                    v2 = f2tf32f(v2); v3 = f2tf32f(v3);
                }
                *(float2*)(C + r0 + col) = make_float2(v0, v1);
                *(float2*)(C + r1 + col) = make_float2(v2, v3);
            }
        }
    }
}

// ---------------- RMSNorm (stores tf32-rounded h) ----------------------------
__global__ __launch_bounds__(256) void rmsnorm_kernel(
    const float* __restrict__ x, const float* __restrict__ nw,
    float* __restrict__ h)
{
    __shared__ float red[8];
    __shared__ float s_scale;
    const int row = blockIdx.x;
    const int t = threadIdx.x;
    const float4 v = ((const float4*)(x + (size_t)row * DM))[t];
    float ss = v.x*v.x + v.y*v.y + v.z*v.z + v.w*v.w;
    #pragma unroll
    for (int o = 16; o > 0; o >>= 1) ss += __shfl_down_sync(0xffffffffu, ss, o);
    if ((t & 31) == 0) red[t >> 5] = ss;
    __syncthreads();
    if (t == 0) {
        float tot = 0.f;
        #pragma unroll
        for (int i = 0; i < 8; i++) tot += red[i];
        s_scale = rsqrtf(tot * (1.0f / DM) + 1e-5f);
    }
    __syncthreads();
    const float sc = s_scale;
    const float4 w = ((const float4*)nw)[t];
    float4 o;
    o.x = f2tf32f(v.x * sc * w.x);
    o.y = f2tf32f(v.y * sc * w.y);
    o.z = f2tf32f(v.z * sc * w.z);
    o.w = f2tf32f(v.w * sc * w.w);
    ((float4*)(h + (size_t)row * DM))[t] = o;
}

// ---------------- depthwise causal conv + bias + SiLU (stores tf32 u) --------
__global__ __launch_bounds__(256) void conv_silu_kernel(
    const float* __restrict__ xz, const float* __restrict__ w,
    const float* __restrict__ bias, float* __restrict__ u)
{
    const long long idx = (long long)blockIdx.x * blockDim.x + threadIdx.x;
    if (idx >= (long long)MROWS * EDIM) return;
    const int e  = (int)(idx & (EDIM - 1));
    const int ml = (int)(idx >> 11);
    const int l  = ml & (SEQL - 1);
    float acc = bias[e];
    const float4 wv = *(const float4*)(w + e * 4);
    const float wk[4] = {wv.x, wv.y, wv.z, wv.w};
    #pragma unroll
    for (int k = 0; k < 4; k++) {
        const int ls = l - 3 + k;
        if (ls >= 0)
            acc = fmaf(xz[(size_t)(ml - 3 + k) * E2 + e], wk[k], acc);
    }
    const float s = 1.f / (1.f + __expf(-acc));
    u[(size_t)ml * EDIM + e] = f2tf32f(acc * s);
}

// ---------------- selective scan (stores tf32 y) ------------------------------
__global__ __launch_bounds__(256) void scan_kernel(
    const float* __restrict__ delta, const float* __restrict__ u,
    const float* __restrict__ dbc,   const float* __restrict__ xz,
    const float* __restrict__ A_log, const float* __restrict__ D_skip,
    float* __restrict__ y)
{
    const int g = blockIdx.x * blockDim.x + threadIdx.x;
    const int chain = g >> 2;
    const int tq = g & 3;
    const int b = chain >> 11;
    const int e = chain & (EDIM - 1);

    float Av[4];
    #pragma unroll
    for (int i = 0; i < 4; i++)
        Av[i] = -__expf(A_log[e * NST + tq * 4 + i]);
    const float Dv = D_skip[e];

    float hs0 = 0.f, hs1 = 0.f, hs2 = 0.f, hs3 = 0.f;
    const size_t base = (size_t)b * SEQL;

    for (int l = 0; l < SEQL; ++l) {
        const size_t r = base + l;
        const float d  = delta[r * EDIM + e];
        const float uu = u[r * EDIM + e];
        const float zz = xz[r * E2 + EDIM + e];
        const float4 Bv = *(const float4*)(dbc + r * FDIM + RDIM + tq * 4);
        const float4 Cv = *(const float4*)(dbc + r * FDIM + RDIM + NST + tq * 4);
        const float du = d * uu;

        hs0 = fmaf(hs0, __expf(d * Av[0]), du * Bv.x);
        hs1 = fmaf(hs1, __expf(d * Av[1]), du * Bv.y);
        hs2 = fmaf(hs2, __expf(d * Av[2]), du * Bv.z);
        hs3 = fmaf(hs3, __expf(d * Av[3]), du * Bv.w);

        float yp = hs0 * Cv.x + hs1 * Cv.y + hs2 * Cv.z + hs3 * Cv.w;
        yp += __shfl_xor_sync(0xffffffffu, yp, 1);
        yp += __shfl_xor_sync(0xffffffffu, yp, 2);

        if (tq == 0) {
            const float sg = 1.f / (1.f + __expf(-zz));
            y[r * EDIM + e] = f2tf32f((yp + uu * Dv) * (zz * sg));
        }
    }
}

// ---------------- launch ------------------------------------------------------
extern "C" void kernel_launch(void* const* d_in, const int* in_sizes, int n_in,
                              void* d_out, int out_size)
{
    const float* x          = (const float*)d_in[0];
    const float* norm_w     = (const float*)d_in[1];
    const float* in_proj_w  = (const float*)d_in[2];
    const float* conv_w     = (const float*)d_in[3];
    const float* conv_b     = (const float*)d_in[4];
    const float* x_proj_w   = (const float*)d_in[5];
    const float* dt_proj_w  = (const float*)d_in[6];
    const float* dt_proj_b  = (const float*)d_in[7];
    const float* A_log      = (const float*)d_in[8];
    const float* D_skip     = (const float*)d_in[9];
    const float* out_proj_w = (const float*)d_in[10];
    float* out = (float*)d_out;

    float *ph, *pxz, *pu, *pdbc, *pdelta, *py;
    float *pw_in, *pw_x, *pw_dt, *pw_out;
    cudaGetSymbolAddress((void**)&ph,     g_h);
    cudaGetSymbolAddress((void**)&pxz,    g_xz);
    cudaGetSymbolAddress((void**)&pu,     g_u);
    cudaGetSymbolAddress((void**)&pdbc,   g_dbc);
    cudaGetSymbolAddress((void**)&pdelta, g_delta);
    cudaGetSymbolAddress((void**)&py,     g_y);
    cudaGetSymbolAddress((void**)&pw_in,  g_w_in);
    cudaGetSymbolAddress((void**)&pw_x,   g_w_x);
    cudaGetSymbolAddress((void**)&pw_dt,  g_w_dt);
    cudaGetSymbolAddress((void**)&pw_out, g_w_out);

    cudaFuncSetAttribute(gemm_mma4, cudaFuncAttributeMaxDynamicSharedMemorySize,
                         GEMM_SMEM_BYTES);

    // 0. pre-round weights to tf32
    {
        const int n_in4  = E2 * DM / 4;
        const int n_x4   = FDIM * EDIM / 4;
        const int n_dt4  = EDIM * RDIM / 4;
        const int n_out4 = DM * EDIM / 4;
        round_tf32_k<<<(n_in4 + 255) / 256, 256>>>(in_proj_w, pw_in, n_in4);
        round_tf32_k<<<(n_x4 + 255) / 256, 256>>>(x_proj_w, pw_x, n_x4);
        round_tf32_k<<<(n_dt4 + 255) / 256, 256>>>(dt_proj_w, pw_dt, n_dt4);
        round_tf32_k<<<(n_out4 + 255) / 256, 256>>>(out_proj_w, pw_out, n_out4);
    }

    // 1. RMSNorm (tf32-rounded h)
    rmsnorm_kernel<<<MROWS, 256>>>(x, norm_w, ph);

    // 2. xz = h @ in_proj_w^T   [16384, 4096]
    {
        dim3 grid(E2 / 128, MROWS / 128);
        gemm_mma4<<<grid, 128, GEMM_SMEM_BYTES>>>(ph, DM, pw_in, pxz,
                                                  MROWS, E2, DM, 0, nullptr, 0);
    }

    // 3. depthwise conv + SiLU -> u (tf32-rounded)
    {
        long long tot = (long long)MROWS * EDIM;
        conv_silu_kernel<<<(unsigned)((tot + 255) / 256), 256>>>(pxz, conv_w, conv_b, pu);
    }

    // 4. dbc = u @ x_proj_w^T  [16384, 96] (tf32-rounded out)
    {
        dim3 grid(1, MROWS / 128);
        gemm_mma4<<<grid, 128, GEMM_SMEM_BYTES>>>(pu, EDIM, pw_x, pdbc,
                                                  MROWS, FDIM, EDIM, 0, nullptr, 1);
    }

    // 5. delta = softplus(dbc[:, :64] @ dt_proj_w^T + b)  [16384, 2048]
    {
        dim3 grid(EDIM / 128, MROWS / 128);
        gemm_mma4<<<grid, 128, GEMM_SMEM_BYTES>>>(pdbc, FDIM, pw_dt, pdelta,
                                                  MROWS, EDIM, RDIM, 1, dt_proj_b, 0);
    }

    // 6. selective scan -> y (tf32-rounded)
    scan_kernel<<<(MROWS * 4) / 256, 256>>>(pdelta, pu, pdbc, pxz, A_log, D_skip, py);

    // 7. out = y @ out_proj_w^T + x   [16384, 1024]
    {
        dim3 grid(DM / 128, MROWS / 128);
        gemm_mma4<<<grid, 128, GEMM_SMEM_BYTES>>>(py, EDIM, pw_out, out,
                                                  MROWS, DM, EDIM, 2, x, 0);
    }
}

// round 5
// speedup vs baseline: 2.2775x; 1.1162x over previous
#include <cuda_runtime.h>
#include <cuda_fp16.h>
#include <math.h>
#include <stdint.h>

#define BATCHN 8
#define SEQL   2048
#define DM     1024
#define EDIM   2048
#define E2     4096
#define NST    16
#define RDIM   64
#define FDIM   96
#define MROWS  (BATCHN*SEQL)   // 16384

// ---------------- scratch (device globals; no runtime allocation) -----------
__device__ float  g_xz[(size_t)MROWS * E2];
__device__ float  g_u[(size_t)MROWS * EDIM];
__device__ float  g_dbc[(size_t)MROWS * FDIM];
__device__ float  g_delta[(size_t)MROWS * EDIM];
__device__ __half g_h_h[(size_t)MROWS * DM];
__device__ __half g_u_h[(size_t)MROWS * EDIM];
__device__ __half g_dbc_h[(size_t)MROWS * FDIM];
__device__ __half g_y_h[(size_t)MROWS * EDIM];
// fp16 weights
__device__ __half g_w_in [(size_t)E2 * DM];
__device__ __half g_w_x  [(size_t)FDIM * EDIM];
__device__ __half g_w_dt [(size_t)EDIM * RDIM];
__device__ __half g_w_out[(size_t)DM * EDIM];

// ---------------- fp32 -> fp16 weight conversion ------------------------------
__global__ __launch_bounds__(256) void conv_f16_k(
    const float* __restrict__ in, __half* __restrict__ out, int n4)
{
    const int i = blockIdx.x * blockDim.x + threadIdx.x;
    if (i < n4) {
        const float4 v = ((const float4*)in)[i];
        __half2 h0 = __floats2half2_rn(v.x, v.y);
        __half2 h1 = __floats2half2_rn(v.z, v.w);
        ((__half2*)out)[i * 2]     = h0;
        ((__half2*)out)[i * 2 + 1] = h1;
    }
}

// ====================== fp16 mma.sync GEMM (cp.async) ========================
// C[M,N] = A[M,K] * B[N,K]^T ; A,B fp16 in gmem (K-major), C fp32.
// mode 0: plain   mode 1: +bias[n], softplus   mode 2: +resid[m*N+n]
// Ch != nullptr: also store fp16 copy of C.
#define STR 40                                // halfs per row (80B, conflict-free)
#define TILE_H (128 * STR)                    // 5120 halfs / matrix / stage
#define STAGE_H (2 * TILE_H)                  // 10240 halfs
#define GEMM_SMEM_BYTES (2 * STAGE_H * 2)     // 40960 bytes (2 stages)

__device__ __forceinline__ void cpa16(uint32_t dst, const void* src, bool pred) {
    const int sz = pred ? 16 : 0;
    asm volatile("cp.async.cg.shared.global [%0], [%1], 16, %2;"
                 :: "r"(dst), "l"(src), "r"(sz));
}
#define CP_COMMIT() asm volatile("cp.async.commit_group;" ::: "memory")
#define CP_WAIT1()  asm volatile("cp.async.wait_group 1;" ::: "memory")

__device__ __forceinline__ void mma_f16(
    float* c, uint32_t a0, uint32_t a1, uint32_t a2, uint32_t a3,
    uint32_t b0, uint32_t b1)
{
    asm volatile(
        "mma.sync.aligned.m16n8k16.row.col.f32.f16.f16.f32 "
        "{%0,%1,%2,%3}, {%4,%5,%6,%7}, {%8,%9}, {%0,%1,%2,%3};"
        : "+f"(c[0]), "+f"(c[1]), "+f"(c[2]), "+f"(c[3])
        : "r"(a0), "r"(a1), "r"(a2), "r"(a3), "r"(b0), "r"(b1));
}

__device__ __forceinline__ uint32_t smem_to_u32(const void* p) {
    uint32_t a;
    asm("{ .reg .u64 t; cvta.to.shared.u64 t, %1; cvt.u32.u64 %0, t; }" : "=r"(a) : "l"(p));
    return a;
}

__global__ __launch_bounds__(128, 2) void gemm_h(
    const __half* __restrict__ A, int lda,
    const __half* __restrict__ B,          // [N, Kd] row-major (K-major)
    float* __restrict__ C,                 // [M, N] fp32
    int M, int N, int Kd,
    int mode, const float* __restrict__ aux,
    __half* __restrict__ Ch)
{
    extern __shared__ __half smh[];
    const uint32_t smem_u = smem_to_u32(smh);
    const int tid  = threadIdx.x;
    const int lane = tid & 31;
    const int wid  = tid >> 5;             // 0..3
    const int wm   = wid >> 1;             // 0..1
    const int wn   = wid & 1;              // 0..1
    const int g    = lane >> 2;            // 0..7
    const int t4   = lane & 3;             // 0..3
    const int bm   = blockIdx.y * 128;
    const int bn   = blockIdx.x * 128;
    const int KT   = Kd >> 5;

    // per-thread copy slots: 4 x 16B chunks per 128x32-half matrix -> 512 chunks,
    // 1024 for A+B, 8 per thread
    int f_row[8], f_c4[8];
    #pragma unroll
    for (int i = 0; i < 8; ++i) {
        const int slot = tid + i * 128;    // 0..1023
        f_row[i] = slot >> 2;              // but slots 512.. map to B
        f_c4[i]  = slot & 3;
    }
    // slots 0..511 -> A rows 0..127, slots 512..1023 -> B rows 0..127
    // handled by i<4 => A, i>=4 => B (128*4=512 slots each)

    // prologue: tile 0
    {
        #pragma unroll
        for (int i = 0; i < 4; ++i) {
            const int row = (tid + i * 128) >> 2;
            const int c4  = (tid + i * 128) & 3;
            const uint32_t off = (uint32_t)(row * STR + c4 * 8) * 2;
            cpa16(smem_u + off, A + (size_t)(bm + row) * lda + c4 * 8, true);
            cpa16(smem_u + TILE_H * 2 + off,
                  B + (size_t)(bn + row) * Kd + c4 * 8, bn + row < N);
        }
        CP_COMMIT();
    }

    float acc[4][8][4];
    #pragma unroll
    for (int m = 0; m < 4; ++m)
        #pragma unroll
        for (int n = 0; n < 8; ++n)
            #pragma unroll
            for (int j = 0; j < 4; ++j) acc[m][n][j] = 0.f;

    for (int kt = 0; kt < KT; ++kt) {
        if (kt + 1 < KT) {
            const int s = (kt + 1) & 1;
            const int kbase = (kt + 1) << 5;
            const uint32_t ab = smem_u + s * (STAGE_H * 2);
            const uint32_t bb = ab + TILE_H * 2;
            #pragma unroll
            for (int i = 0; i < 4; ++i) {
                const int row = (tid + i * 128) >> 2;
                const int c4  = (tid + i * 128) & 3;
                const uint32_t off = (uint32_t)(row * STR + c4 * 8) * 2;
                cpa16(ab + off, A + (size_t)(bm + row) * lda + kbase + c4 * 8, true);
                cpa16(bb + off, B + (size_t)(bn + row) * Kd + kbase + c4 * 8,
                      bn + row < N);
            }
        }
        CP_COMMIT();
        CP_WAIT1();
        __syncthreads();

        const __half* as = smh + (kt & 1) * STAGE_H + (wm * 64) * STR;
        const __half* bs = smh + (kt & 1) * STAGE_H + TILE_H + (wn * 64) * STR;
        #pragma unroll
        for (int ks = 0; ks < 2; ++ks) {
            const int k16 = ks * 16;
            uint32_t a[4][4];
            #pragma unroll
            for (int m = 0; m < 4; ++m) {
                const __half* ap = as + (m * 16) * STR;
                a[m][0] = *(const uint32_t*)(ap + (g    ) * STR + k16 + 2 * t4);
                a[m][1] = *(const uint32_t*)(ap + (g + 8) * STR + k16 + 2 * t4);
                a[m][2] = *(const uint32_t*)(ap + (g    ) * STR + k16 + 2 * t4 + 8);
                a[m][3] = *(const uint32_t*)(ap + (g + 8) * STR + k16 + 2 * t4 + 8);
            }
            uint32_t b[8][2];
            #pragma unroll
            for (int n = 0; n < 8; ++n) {
                const __half* bp = bs + (n * 8) * STR;
                b[n][0] = *(const uint32_t*)(bp + g * STR + k16 + 2 * t4);
                b[n][1] = *(const uint32_t*)(bp + g * STR + k16 + 2 * t4 + 8);
            }
            #pragma unroll
            for (int m = 0; m < 4; ++m)
                #pragma unroll
                for (int n = 0; n < 8; ++n)
                    mma_f16(acc[m][n], a[m][0], a[m][1], a[m][2], a[m][3],
                            b[n][0], b[n][1]);
        }
        __syncthreads();
    }

    // ---- epilogue ----
    #pragma unroll
    for (int m = 0; m < 4; ++m) {
        const int row0 = bm + wm * 64 + m * 16 + g;
        const size_t r0 = (size_t)row0 * N;
        const size_t r1 = (size_t)(row0 + 8) * N;
        #pragma unroll
        for (int n = 0; n < 8; ++n) {
            const int col = bn + wn * 64 + n * 8 + 2 * t4;
            if (col < N) {
                float v0 = acc[m][n][0], v1 = acc[m][n][1];
                float v2 = acc[m][n][2], v3 = acc[m][n][3];
                if (mode == 1) {
                    const float b0 = aux[col], b1 = aux[col + 1];
                    v0 += b0; v1 += b1; v2 += b0; v3 += b1;
                    v0 = fmaxf(v0, 0.f) + log1pf(__expf(-fabsf(v0)));
                    v1 = fmaxf(v1, 0.f) + log1pf(__expf(-fabsf(v1)));
                    v2 = fmaxf(v2, 0.f) + log1pf(__expf(-fabsf(v2)));
                    v3 = fmaxf(v3, 0.f) + log1pf(__expf(-fabsf(v3)));
                } else if (mode == 2) {
                    const float2 x0 = *(const float2*)(aux + r0 + col);
                    const float2 x1 = *(const float2*)(aux + r1 + col);
                    v0 += x0.x; v1 += x0.y; v2 += x1.x; v3 += x1.y;
                }
                *(float2*)(C + r0 + col) = make_float2(v0, v1);
                *(float2*)(C + r1 + col) = make_float2(v2, v3);
                if (Ch) {
                    *(__half2*)(Ch + r0 + col) = __floats2half2_rn(v0, v1);
                    *(__half2*)(Ch + r1 + col) = __floats2half2_rn(v2, v3);
                }
            }
        }
    }
}

// ---------------- RMSNorm (stores fp16 h) ------------------------------------
__global__ __launch_bounds__(256) void rmsnorm_kernel(
    const float* __restrict__ x, const float* __restrict__ nw,
    __half* __restrict__ h)
{
    __shared__ float red[8];
    __shared__ float s_scale;
    const int row = blockIdx.x;
    const int t = threadIdx.x;
    const float4 v = ((const float4*)(x + (size_t)row * DM))[t];
    float ss = v.x*v.x + v.y*v.y + v.z*v.z + v.w*v.w;
    #pragma unroll
    for (int o = 16; o > 0; o >>= 1) ss += __shfl_down_sync(0xffffffffu, ss, o);
    if ((t & 31) == 0) red[t >> 5] = ss;
    __syncthreads();
    if (t == 0) {
        float tot = 0.f;
        #pragma unroll
        for (int i = 0; i < 8; i++) tot += red[i];
        s_scale = rsqrtf(tot * (1.0f / DM) + 1e-5f);
    }
    __syncthreads();
    const float sc = s_scale;
    const float4 w = ((const float4*)nw)[t];
    __half2 h0 = __floats2half2_rn(v.x * sc * w.x, v.y * sc * w.y);
    __half2 h1 = __floats2half2_rn(v.z * sc * w.z, v.w * sc * w.w);
    ((__half2*)(h + (size_t)row * DM))[t * 2]     = h0;
    ((__half2*)(h + (size_t)row * DM))[t * 2 + 1] = h1;
}

// ---------------- depthwise causal conv + bias + SiLU ------------------------
__global__ __launch_bounds__(256) void conv_silu_kernel(
    const float* __restrict__ xz, const float* __restrict__ w,
    const float* __restrict__ bias, float* __restrict__ u,
    __half* __restrict__ uh)
{
    const long long idx = (long long)blockIdx.x * blockDim.x + threadIdx.x;
    if (idx >= (long long)MROWS * EDIM) return;
    const int e  = (int)(idx & (EDIM - 1));
    const int ml = (int)(idx >> 11);
    const int l  = ml & (SEQL - 1);
    float acc = bias[e];
    const float4 wv = *(const float4*)(w + e * 4);
    const float wk[4] = {wv.x, wv.y, wv.z, wv.w};
    #pragma unroll
    for (int k = 0; k < 4; k++) {
        const int ls = l - 3 + k;
        if (ls >= 0)
            acc = fmaf(xz[(size_t)(ml - 3 + k) * E2 + e], wk[k], acc);
    }
    const float s = 1.f / (1.f + __expf(-acc));
    const float uv = acc * s;
    u[(size_t)ml * EDIM + e]  = uv;
    uh[(size_t)ml * EDIM + e] = __float2half_rn(uv);
}

// ---------------- selective scan (stores fp16 y) ------------------------------
__global__ __launch_bounds__(256) void scan_kernel(
    const float* __restrict__ delta, const float* __restrict__ u,
    const float* __restrict__ dbc,   const float* __restrict__ xz,
    const float* __restrict__ A_log, const float* __restrict__ D_skip,
    __half* __restrict__ y)
{
    const int g = blockIdx.x * blockDim.x + threadIdx.x;
    const int chain = g >> 2;
    const int tq = g & 3;
    const int b = chain >> 11;
    const int e = chain & (EDIM - 1);

    float Av[4];
    #pragma unroll
    for (int i = 0; i < 4; i++)
        Av[i] = -__expf(A_log[e * NST + tq * 4 + i]);
    const float Dv = D_skip[e];

    float hs0 = 0.f, hs1 = 0.f, hs2 = 0.f, hs3 = 0.f;
    const size_t base = (size_t)b * SEQL;

    for (int l = 0; l < SEQL; ++l) {
        const size_t r = base + l;
        const float d  = delta[r * EDIM + e];
        const float uu = u[r * EDIM + e];
        const float zz = xz[r * E2 + EDIM + e];
        const float4 Bv = *(const float4*)(dbc + r * FDIM + RDIM + tq * 4);
        const float4 Cv = *(const float4*)(dbc + r * FDIM + RDIM + NST + tq * 4);
        const float du = d * uu;

        hs0 = fmaf(hs0, __expf(d * Av[0]), du * Bv.x);
        hs1 = fmaf(hs1, __expf(d * Av[1]), du * Bv.y);
        hs2 = fmaf(hs2, __expf(d * Av[2]), du * Bv.z);
        hs3 = fmaf(hs3, __expf(d * Av[3]), du * Bv.w);

        float yp = hs0 * Cv.x + hs1 * Cv.y + hs2 * Cv.z + hs3 * Cv.w;
        yp += __shfl_xor_sync(0xffffffffu, yp, 1);
        yp += __shfl_xor_sync(0xffffffffu, yp, 2);

        if (tq == 0) {
            const float sg = 1.f / (1.f + __expf(-zz));
            y[r * EDIM + e] = __float2half_rn((yp + uu * Dv) * (zz * sg));
        }
    }
}

// ---------------- launch ------------------------------------------------------
extern "C" void kernel_launch(void* const* d_in, const int* in_sizes, int n_in,
                              void* d_out, int out_size)
{
    const float* x          = (const float*)d_in[0];
    const float* norm_w     = (const float*)d_in[1];
    const float* in_proj_w  = (const float*)d_in[2];
    const float* conv_w     = (const float*)d_in[3];
    const float* conv_b     = (const float*)d_in[4];
    const float* x_proj_w   = (const float*)d_in[5];
    const float* dt_proj_w  = (const float*)d_in[6];
    const float* dt_proj_b  = (const float*)d_in[7];
    const float* A_log      = (const float*)d_in[8];
    const float* D_skip     = (const float*)d_in[9];
    const float* out_proj_w = (const float*)d_in[10];
    float* out = (float*)d_out;

    float *pxz, *pu, *pdbc, *pdelta;
    __half *ph_h, *pu_h, *pdbc_h, *py_h;
    __half *pw_in, *pw_x, *pw_dt, *pw_out;
    cudaGetSymbolAddress((void**)&pxz,    g_xz);
    cudaGetSymbolAddress((void**)&pu,     g_u);
    cudaGetSymbolAddress((void**)&pdbc,   g_dbc);
    cudaGetSymbolAddress((void**)&pdelta, g_delta);
    cudaGetSymbolAddress((void**)&ph_h,   g_h_h);
    cudaGetSymbolAddress((void**)&pu_h,   g_u_h);
    cudaGetSymbolAddress((void**)&pdbc_h, g_dbc_h);
    cudaGetSymbolAddress((void**)&py_h,   g_y_h);
    cudaGetSymbolAddress((void**)&pw_in,  g_w_in);
    cudaGetSymbolAddress((void**)&pw_x,   g_w_x);
    cudaGetSymbolAddress((void**)&pw_dt,  g_w_dt);
    cudaGetSymbolAddress((void**)&pw_out, g_w_out);

    cudaFuncSetAttribute(gemm_h, cudaFuncAttributeMaxDynamicSharedMemorySize,
                         GEMM_SMEM_BYTES);

    // 0. convert weights to fp16
    {
        const int n_in4  = E2 * DM / 4;
        const int n_x4   = FDIM * EDIM / 4;
        const int n_dt4  = EDIM * RDIM / 4;
        const int n_out4 = DM * EDIM / 4;
        conv_f16_k<<<(n_in4 + 255) / 256, 256>>>(in_proj_w, pw_in, n_in4);
        conv_f16_k<<<(n_x4 + 255) / 256, 256>>>(x_proj_w, pw_x, n_x4);
        conv_f16_k<<<(n_dt4 + 255) / 256, 256>>>(dt_proj_w, pw_dt, n_dt4);
        conv_f16_k<<<(n_out4 + 255) / 256, 256>>>(out_proj_w, pw_out, n_out4);
    }

    // 1. RMSNorm -> h (fp16)
    rmsnorm_kernel<<<MROWS, 256>>>(x, norm_w, ph_h);

    // 2. xz = h @ in_proj_w^T   [16384, 4096] fp32
    {
        dim3 grid(E2 / 128, MROWS / 128);
        gemm_h<<<grid, 128, GEMM_SMEM_BYTES>>>(ph_h, DM, pw_in, pxz,
                                               MROWS, E2, DM, 0, nullptr, nullptr);
    }

    // 3. depthwise conv + SiLU -> u (fp32 + fp16)
    {
        long long tot = (long long)MROWS * EDIM;
        conv_silu_kernel<<<(unsigned)((tot + 255) / 256), 256>>>(pxz, conv_w, conv_b,
                                                                 pu, pu_h);
    }

    // 4. dbc = u @ x_proj_w^T  [16384, 96] (fp32 + fp16)
    {
        dim3 grid(1, MROWS / 128);
        gemm_h<<<grid, 128, GEMM_SMEM_BYTES>>>(pu_h, EDIM, pw_x, pdbc,
                                               MROWS, FDIM, EDIM, 0, nullptr, pdbc_h);
    }

    // 5. delta = softplus(dbc[:, :64] @ dt_proj_w^T + b)  [16384, 2048] fp32
    {
        dim3 grid(EDIM / 128, MROWS / 128);
        gemm_h<<<grid, 128, GEMM_SMEM_BYTES>>>(pdbc_h, FDIM, pw_dt, pdelta,
                                               MROWS, EDIM, RDIM, 1, dt_proj_b, nullptr);
    }

    // 6. selective scan -> y (fp16)
    scan_kernel<<<(MROWS * 4) / 256, 256>>>(pdelta, pu, pdbc, pxz, A_log, D_skip, py_h);

    // 7. out = y @ out_proj_w^T + x   [16384, 1024] fp32
    {
        dim3 grid(DM / 128, MROWS / 128);
        gemm_h<<<grid, 128, GEMM_SMEM_BYTES>>>(py_h, EDIM, pw_out, out,
                                               MROWS, DM, EDIM, 2, x, nullptr);
    }
}

// round 6
// speedup vs baseline: 2.2812x; 1.0016x over previous
#include <cuda_runtime.h>
#include <cuda_fp16.h>
#include <math.h>
#include <stdint.h>

#define BATCHN 8
#define SEQL   2048
#define DM     1024
#define EDIM   2048
#define E2     4096
#define NST    16
#define RDIM   64
#define FDIM   96
#define MROWS  (BATCHN*SEQL)   // 16384

// ---------------- scratch (device globals; no runtime allocation) -----------
__device__ float  g_xz[(size_t)MROWS * E2];
__device__ float  g_u[(size_t)MROWS * EDIM];
__device__ float  g_dbc[(size_t)MROWS * FDIM];
__device__ float  g_delta[(size_t)MROWS * EDIM];
__device__ __half g_h_h[(size_t)MROWS * DM];
__device__ __half g_u_h[(size_t)MROWS * EDIM];
__device__ __half g_dbc_h[(size_t)MROWS * FDIM];
__device__ __half g_y_h[(size_t)MROWS * EDIM];
// fp16 weights
__device__ __half g_w_in [(size_t)E2 * DM];
__device__ __half g_w_x  [(size_t)FDIM * EDIM];
__device__ __half g_w_dt [(size_t)EDIM * RDIM];
__device__ __half g_w_out[(size_t)DM * EDIM];

// ---------------- fp32 -> fp16 weight conversion ------------------------------
__global__ __launch_bounds__(256) void conv_f16_k(
    const float* __restrict__ in, __half* __restrict__ out, int n4)
{
    const int i = blockIdx.x * blockDim.x + threadIdx.x;
    if (i < n4) {
        const float4 v = ((const float4*)in)[i];
        __half2 h0 = __floats2half2_rn(v.x, v.y);
        __half2 h1 = __floats2half2_rn(v.z, v.w);
        ((__half2*)out)[i * 2]     = h0;
        ((__half2*)out)[i * 2 + 1] = h1;
    }
}

// ====================== fp16 mma.sync GEMM (cp.async) ========================
// C[M,N] = A[M,K] * B[N,K]^T ; A,B fp16 in gmem (K-major), C fp32.
// mode 0: plain   mode 1: +bias[n], softplus   mode 2: +resid[m*N+n]
// Ch != nullptr: also store fp16 copy of C.
#define STR 40                                // halfs per row (80B, conflict-free)
#define TILE_H (128 * STR)                    // 5120 halfs / matrix / stage
#define STAGE_H (2 * TILE_H)                  // 10240 halfs
#define GEMM_SMEM_BYTES (2 * STAGE_H * 2)     // 40960 bytes (2 stages)

__device__ __forceinline__ void cpa16(uint32_t dst, const void* src, bool pred) {
    const int sz = pred ? 16 : 0;
    asm volatile("cp.async.cg.shared.global [%0], [%1], 16, %2;"
                 :: "r"(dst), "l"(src), "r"(sz));
}
#define CP_COMMIT() asm volatile("cp.async.commit_group;" ::: "memory")
#define CP_WAIT1()  asm volatile("cp.async.wait_group 1;" ::: "memory")

__device__ __forceinline__ void mma_f16(
    float* c, uint32_t a0, uint32_t a1, uint32_t a2, uint32_t a3,
    uint32_t b0, uint32_t b1)
{
    asm volatile(
        "mma.sync.aligned.m16n8k16.row.col.f32.f16.f16.f32 "
        "{%0,%1,%2,%3}, {%4,%5,%6,%7}, {%8,%9}, {%0,%1,%2,%3};"
        : "+f"(c[0]), "+f"(c[1]), "+f"(c[2]), "+f"(c[3])
        : "r"(a0), "r"(a1), "r"(a2), "r"(a3), "r"(b0), "r"(b1));
}

__device__ __forceinline__ uint32_t smem_to_u32(const void* p) {
    uint32_t a;
    asm("{ .reg .u64 t; cvta.to.shared.u64 t, %1; cvt.u32.u64 %0, t; }" : "=r"(a) : "l"(p));
    return a;
}

__global__ __launch_bounds__(128, 2) void gemm_h(
    const __half* __restrict__ A, int lda,
    const __half* __restrict__ B,          // [N, Kd] row-major (K-major)
    float* __restrict__ C,                 // [M, N] fp32
    int M, int N, int Kd,
    int mode, const float* __restrict__ aux,
    __half* __restrict__ Ch)
{
    extern __shared__ __half smh[];
    const uint32_t smem_u = smem_to_u32(smh);
    const int tid  = threadIdx.x;
    const int lane = tid & 31;
    const int wid  = tid >> 5;             // 0..3
    const int wm   = wid >> 1;             // 0..1
    const int wn   = wid & 1;              // 0..1
    const int g    = lane >> 2;            // 0..7
    const int t4   = lane & 3;             // 0..3
    const int bm   = blockIdx.y * 128;
    const int bn   = blockIdx.x * 128;
    const int KT   = Kd >> 5;

    // per-thread copy slots: 4 x 16B chunks per 128x32-half matrix -> 512 chunks,
    // 1024 for A+B, 8 per thread
    int f_row[8], f_c4[8];
    #pragma unroll
    for (int i = 0; i < 8; ++i) {
        const int slot = tid + i * 128;    // 0..1023
        f_row[i] = slot >> 2;              // but slots 512.. map to B
        f_c4[i]  = slot & 3;
    }
    // slots 0..511 -> A rows 0..127, slots 512..1023 -> B rows 0..127
    // handled by i<4 => A, i>=4 => B (128*4=512 slots each)

    // prologue: tile 0
    {
        #pragma unroll
        for (int i = 0; i < 4; ++i) {
            const int row = (tid + i * 128) >> 2;
            const int c4  = (tid + i * 128) & 3;
            const uint32_t off = (uint32_t)(row * STR + c4 * 8) * 2;
            cpa16(smem_u + off, A + (size_t)(bm + row) * lda + c4 * 8, true);
            cpa16(smem_u + TILE_H * 2 + off,
                  B + (size_t)(bn + row) * Kd + c4 * 8, bn + row < N);
        }
        CP_COMMIT();
    }

    float acc[4][8][4];
    #pragma unroll
    for (int m = 0; m < 4; ++m)
        #pragma unroll
        for (int n = 0; n < 8; ++n)
            #pragma unroll
            for (int j = 0; j < 4; ++j) acc[m][n][j] = 0.f;

    for (int kt = 0; kt < KT; ++kt) {
        if (kt + 1 < KT) {
            const int s = (kt + 1) & 1;
            const int kbase = (kt + 1) << 5;
            const uint32_t ab = smem_u + s * (STAGE_H * 2);
            const uint32_t bb = ab + TILE_H * 2;
            #pragma unroll
            for (int i = 0; i < 4; ++i) {
                const int row = (tid + i * 128) >> 2;
                const int c4  = (tid + i * 128) & 3;
                const uint32_t off = (uint32_t)(row * STR + c4 * 8) * 2;
                cpa16(ab + off, A + (size_t)(bm + row) * lda + kbase + c4 * 8, true);
                cpa16(bb + off, B + (size_t)(bn + row) * Kd + kbase + c4 * 8,
                      bn + row < N);
            }
        }
        CP_COMMIT();
        CP_WAIT1();
        __syncthreads();

        const __half* as = smh + (kt & 1) * STAGE_H + (wm * 64) * STR;
        const __half* bs = smh + (kt & 1) * STAGE_H + TILE_H + (wn * 64) * STR;
        #pragma unroll
        for (int ks = 0; ks < 2; ++ks) {
            const int k16 = ks * 16;
            uint32_t a[4][4];
            #pragma unroll
            for (int m = 0; m < 4; ++m) {
                const __half* ap = as + (m * 16) * STR;
                a[m][0] = *(const uint32_t*)(ap + (g    ) * STR + k16 + 2 * t4);
                a[m][1] = *(const uint32_t*)(ap + (g + 8) * STR + k16 + 2 * t4);
                a[m][2] = *(const uint32_t*)(ap + (g    ) * STR + k16 + 2 * t4 + 8);
                a[m][3] = *(const uint32_t*)(ap + (g + 8) * STR + k16 + 2 * t4 + 8);
            }
            uint32_t b[8][2];
            #pragma unroll
            for (int n = 0; n < 8; ++n) {
                const __half* bp = bs + (n * 8) * STR;
                b[n][0] = *(const uint32_t*)(bp + g * STR + k16 + 2 * t4);
                b[n][1] = *(const uint32_t*)(bp + g * STR + k16 + 2 * t4 + 8);
            }
            #pragma unroll
            for (int m = 0; m < 4; ++m)
                #pragma unroll
                for (int n = 0; n < 8; ++n)
                    mma_f16(acc[m][n], a[m][0], a[m][1], a[m][2], a[m][3],
                            b[n][0], b[n][1]);
        }
        __syncthreads();
    }

    // ---- epilogue ----
    #pragma unroll
    for (int m = 0; m < 4; ++m) {
        const int row0 = bm + wm * 64 + m * 16 + g;
        const size_t r0 = (size_t)row0 * N;
        const size_t r1 = (size_t)(row0 + 8) * N;
        #pragma unroll
        for (int n = 0; n < 8; ++n) {
            const int col = bn + wn * 64 + n * 8 + 2 * t4;
            if (col < N) {
                float v0 = acc[m][n][0], v1 = acc[m][n][1];
                float v2 = acc[m][n][2], v3 = acc[m][n][3];
                if (mode == 1) {
                    const float b0 = aux[col], b1 = aux[col + 1];
                    v0 += b0; v1 += b1; v2 += b0; v3 += b1;
                    v0 = fmaxf(v0, 0.f) + log1pf(__expf(-fabsf(v0)));
                    v1 = fmaxf(v1, 0.f) + log1pf(__expf(-fabsf(v1)));
                    v2 = fmaxf(v2, 0.f) + log1pf(__expf(-fabsf(v2)));
                    v3 = fmaxf(v3, 0.f) + log1pf(__expf(-fabsf(v3)));
                } else if (mode == 2) {
                    const float2 x0 = *(const float2*)(aux + r0 + col);
                    const float2 x1 = *(const float2*)(aux + r1 + col);
                    v0 += x0.x; v1 += x0.y; v2 += x1.x; v3 += x1.y;
                }
                *(float2*)(C + r0 + col) = make_float2(v0, v1);
                *(float2*)(C + r1 + col) = make_float2(v2, v3);
                if (Ch) {
                    *(__half2*)(Ch + r0 + col) = __floats2half2_rn(v0, v1);
                    *(__half2*)(Ch + r1 + col) = __floats2half2_rn(v2, v3);
                }
            }
        }
    }
}

// ---------------- RMSNorm (stores fp16 h) ------------------------------------
__global__ __launch_bounds__(256) void rmsnorm_kernel(
    const float* __restrict__ x, const float* __restrict__ nw,
    __half* __restrict__ h)
{
    __shared__ float red[8];
    __shared__ float s_scale;
    const int row = blockIdx.x;
    const int t = threadIdx.x;
    const float4 v = ((const float4*)(x + (size_t)row * DM))[t];
    float ss = v.x*v.x + v.y*v.y + v.z*v.z + v.w*v.w;
    #pragma unroll
    for (int o = 16; o > 0; o >>= 1) ss += __shfl_down_sync(0xffffffffu, ss, o);
    if ((t & 31) == 0) red[t >> 5] = ss;
    __syncthreads();
    if (t == 0) {
        float tot = 0.f;
        #pragma unroll
        for (int i = 0; i < 8; i++) tot += red[i];
        s_scale = rsqrtf(tot * (1.0f / DM) + 1e-5f);
    }
    __syncthreads();
    const float sc = s_scale;
    const float4 w = ((const float4*)nw)[t];
    __half2 h0 = __floats2half2_rn(v.x * sc * w.x, v.y * sc * w.y);
    __half2 h1 = __floats2half2_rn(v.z * sc * w.z, v.w * sc * w.w);
    ((__half2*)(h + (size_t)row * DM))[t * 2]     = h0;
    ((__half2*)(h + (size_t)row * DM))[t * 2 + 1] = h1;
}

// ---------------- depthwise causal conv + bias + SiLU ------------------------
__global__ __launch_bounds__(256) void conv_silu_kernel(
    const float* __restrict__ xz, const float* __restrict__ w,
    const float* __restrict__ bias, float* __restrict__ u,
    __half* __restrict__ uh)
{
    const long long idx = (long long)blockIdx.x * blockDim.x + threadIdx.x;
    if (idx >= (long long)MROWS * EDIM) return;
    const int e  = (int)(idx & (EDIM - 1));
    const int ml = (int)(idx >> 11);
    const int l  = ml & (SEQL - 1);
    float acc = bias[e];
    const float4 wv = *(const float4*)(w + e * 4);
    const float wk[4] = {wv.x, wv.y, wv.z, wv.w};
    #pragma unroll
    for (int k = 0; k < 4; k++) {
        const int ls = l - 3 + k;
        if (ls >= 0)
            acc = fmaf(xz[(size_t)(ml - 3 + k) * E2 + e], wk[k], acc);
    }
    const float s = 1.f / (1.f + __expf(-acc));
    const float uv = acc * s;
    u[(size_t)ml * EDIM + e]  = uv;
    uh[(size_t)ml * EDIM + e] = __float2half_rn(uv);
}

// ---------------- selective scan (stores fp16 y) ------------------------------
__global__ __launch_bounds__(256) void scan_kernel(
    const float* __restrict__ delta, const float* __restrict__ u,
    const float* __restrict__ dbc,   const float* __restrict__ xz,
    const float* __restrict__ A_log, const float* __restrict__ D_skip,
    __half* __restrict__ y)
{
    const int g = blockIdx.x * blockDim.x + threadIdx.x;
    const int chain = g >> 2;
    const int tq = g & 3;
    const int b = chain >> 11;
    const int e = chain & (EDIM - 1);

    float Av[4];
    #pragma unroll
    for (int i = 0; i < 4; i++)
        Av[i] = -__expf(A_log[e * NST + tq * 4 + i]);
    const float Dv = D_skip[e];

    float hs0 = 0.f, hs1 = 0.f, hs2 = 0.f, hs3 = 0.f;
    const size_t base = (size_t)b * SEQL;

    for (int l = 0; l < SEQL; ++l) {
        const size_t r = base + l;
        const float d  = delta[r * EDIM + e];
        const float uu = u[r * EDIM + e];
        const float zz = xz[r * E2 + EDIM + e];
        const float4 Bv = *(const float4*)(dbc + r * FDIM + RDIM + tq * 4);
        const float4 Cv = *(const float4*)(dbc + r * FDIM + RDIM + NST + tq * 4);
        const float du = d * uu;

        hs0 = fmaf(hs0, __expf(d * Av[0]), du * Bv.x);
        hs1 = fmaf(hs1, __expf(d * Av[1]), du * Bv.y);
        hs2 = fmaf(hs2, __expf(d * Av[2]), du * Bv.z);
        hs3 = fmaf(hs3, __expf(d * Av[3]), du * Bv.w);

        float yp = hs0 * Cv.x + hs1 * Cv.y + hs2 * Cv.z + hs3 * Cv.w;
        yp += __shfl_xor_sync(0xffffffffu, yp, 1);
        yp += __shfl_xor_sync(0xffffffffu, yp, 2);

        if (tq == 0) {
            const float sg = 1.f / (1.f + __expf(-zz));
            y[r * EDIM + e] = __float2half_rn((yp + uu * Dv) * (zz * sg));
        }
    }
}

// ---------------- launch ------------------------------------------------------
extern "C" void kernel_launch(void* const* d_in, const int* in_sizes, int n_in,
                              void* d_out, int out_size)
{
    const float* x          = (const float*)d_in[0];
    const float* norm_w     = (const float*)d_in[1];
    const float* in_proj_w  = (const float*)d_in[2];
    const float* conv_w     = (const float*)d_in[3];
    const float* conv_b     = (const float*)d_in[4];
    const float* x_proj_w   = (const float*)d_in[5];
    const float* dt_proj_w  = (const float*)d_in[6];
    const float* dt_proj_b  = (const float*)d_in[7];
    const float* A_log      = (const float*)d_in[8];
    const float* D_skip     = (const float*)d_in[9];
    const float* out_proj_w = (const float*)d_in[10];
    float* out = (float*)d_out;

    float *pxz, *pu, *pdbc, *pdelta;
    __half *ph_h, *pu_h, *pdbc_h, *py_h;
    __half *pw_in, *pw_x, *pw_dt, *pw_out;
    cudaGetSymbolAddress((void**)&pxz,    g_xz);
    cudaGetSymbolAddress((void**)&pu,     g_u);
    cudaGetSymbolAddress((void**)&pdbc,   g_dbc);
    cudaGetSymbolAddress((void**)&pdelta, g_delta);
    cudaGetSymbolAddress((void**)&ph_h,   g_h_h);
    cudaGetSymbolAddress((void**)&pu_h,   g_u_h);
    cudaGetSymbolAddress((void**)&pdbc_h, g_dbc_h);
    cudaGetSymbolAddress((void**)&py_h,   g_y_h);
    cudaGetSymbolAddress((void**)&pw_in,  g_w_in);
    cudaGetSymbolAddress((void**)&pw_x,   g_w_x);
    cudaGetSymbolAddress((void**)&pw_dt,  g_w_dt);
    cudaGetSymbolAddress((void**)&pw_out, g_w_out);

    cudaFuncSetAttribute(gemm_h, cudaFuncAttributeMaxDynamicSharedMemorySize,
                         GEMM_SMEM_BYTES);

    // 0. convert weights to fp16
    {
        const int n_in4  = E2 * DM / 4;
        const int n_x4   = FDIM * EDIM / 4;
        const int n_dt4  = EDIM * RDIM / 4;
        const int n_out4 = DM * EDIM / 4;
        conv_f16_k<<<(n_in4 + 255) / 256, 256>>>(in_proj_w, pw_in, n_in4);
        conv_f16_k<<<(n_x4 + 255) / 256, 256>>>(x_proj_w, pw_x, n_x4);
        conv_f16_k<<<(n_dt4 + 255) / 256, 256>>>(dt_proj_w, pw_dt, n_dt4);
        conv_f16_k<<<(n_out4 + 255) / 256, 256>>>(out_proj_w, pw_out, n_out4);
    }

    // 1. RMSNorm -> h (fp16)
    rmsnorm_kernel<<<MROWS, 256>>>(x, norm_w, ph_h);

    // 2. xz = h @ in_proj_w^T   [16384, 4096] fp32
    {
        dim3 grid(E2 / 128, MROWS / 128);
        gemm_h<<<grid, 128, GEMM_SMEM_BYTES>>>(ph_h, DM, pw_in, pxz,
                                               MROWS, E2, DM, 0, nullptr, nullptr);
    }

    // 3. depthwise conv + SiLU -> u (fp32 + fp16)
    {
        long long tot = (long long)MROWS * EDIM;
        conv_silu_kernel<<<(unsigned)((tot + 255) / 256), 256>>>(pxz, conv_w, conv_b,
                                                                 pu, pu_h);
    }

    // 4. dbc = u @ x_proj_w^T  [16384, 96] (fp32 + fp16)
    {
        dim3 grid(1, MROWS / 128);
        gemm_h<<<grid, 128, GEMM_SMEM_BYTES>>>(pu_h, EDIM, pw_x, pdbc,
                                               MROWS, FDIM, EDIM, 0, nullptr, pdbc_h);
    }

    // 5. delta = softplus(dbc[:, :64] @ dt_proj_w^T + b)  [16384, 2048] fp32
    {
        dim3 grid(EDIM / 128, MROWS / 128);
        gemm_h<<<grid, 128, GEMM_SMEM_BYTES>>>(pdbc_h, FDIM, pw_dt, pdelta,
                                               MROWS, EDIM, RDIM, 1, dt_proj_b, nullptr);
    }

    // 6. selective scan -> y (fp16)
    scan_kernel<<<(MROWS * 4) / 256, 256>>>(pdelta, pu, pdbc, pxz, A_log, D_skip, py_h);

    // 7. out = y @ out_proj_w^T + x   [16384, 1024] fp32
    {
        dim3 grid(DM / 128, MROWS / 128);
        gemm_h<<<grid, 128, GEMM_SMEM_BYTES>>>(py_h, EDIM, pw_out, out,
                                               MROWS, DM, EDIM, 2, x, nullptr);
    }
}

// round 7
// speedup vs baseline: 3.7038x; 1.6236x over previous
#include <cuda_runtime.h>
#include <cuda_fp16.h>
#include <math.h>
#include <stdint.h>

#define BATCHN 8
#define SEQL   2048
#define DM     1024
#define EDIM   2048
#define E2     4096
#define NST    16
#define RDIM   64
#define FDIM   96
#define MROWS  (BATCHN*SEQL)   // 16384

// ---------------- scratch (device globals; no runtime allocation) -----------
__device__ __half g_xz_h[(size_t)MROWS * E2];      // in_proj out (fp16 only)
__device__ float  g_u[(size_t)MROWS * EDIM];
__device__ float  g_dbc[(size_t)MROWS * FDIM];
__device__ float  g_delta[(size_t)MROWS * EDIM];
__device__ __half g_h_h[(size_t)MROWS * DM];
__device__ __half g_u_h[(size_t)MROWS * EDIM];
__device__ __half g_dbc_h[(size_t)MROWS * FDIM];
__device__ __half g_y_h[(size_t)MROWS * EDIM];
// fp16 weights
__device__ __half g_w_in [(size_t)E2 * DM];
__device__ __half g_w_x  [(size_t)FDIM * EDIM];
__device__ __half g_w_dt [(size_t)EDIM * RDIM];
__device__ __half g_w_out[(size_t)DM * EDIM];

// ---------------- fp32 -> fp16 weight conversion ------------------------------
__global__ __launch_bounds__(256) void conv_f16_k(
    const float* __restrict__ in, __half* __restrict__ out, int n4)
{
    const int i = blockIdx.x * blockDim.x + threadIdx.x;
    if (i < n4) {
        const float4 v = ((const float4*)in)[i];
        ((__half2*)out)[i * 2]     = __floats2half2_rn(v.x, v.y);
        ((__half2*)out)[i * 2 + 1] = __floats2half2_rn(v.z, v.w);
    }
}

// ====================== fp16 mma.sync GEMM v3 ================================
// C[M,N] = A[M,K] * B[N,K]^T ; fp16 operands, fp32 accum.
// 256 thr, 8 warps (2m x 4n), warp tile 64x32, CTA 128x128, 3-stage cp.async,
// ldmatrix fragment loads.  mode 0: plain  1: +bias,softplus  2: +resid
// C (fp32) and/or Ch (fp16) stores, each optional.
#define STR 40                                 // halfs per smem row
#define TILE_BYTES (128 * STR * 2)             // 10240
#define STAGE_BYTES (2 * TILE_BYTES)           // 20480
#define NSTAGE 3
#define GEMM_SMEM_BYTES (NSTAGE * STAGE_BYTES) // 61440

__device__ __forceinline__ void cpa16(uint32_t dst, const void* src, bool pred) {
    const int sz = pred ? 16 : 0;
    asm volatile("cp.async.cg.shared.global [%0], [%1], 16, %2;"
                 :: "r"(dst), "l"(src), "r"(sz));
}
#define CP_COMMIT() asm volatile("cp.async.commit_group;" ::: "memory")
#define CP_WAIT2()  asm volatile("cp.async.wait_group 2;" ::: "memory")

__device__ __forceinline__ void ldm_x4(uint32_t* r, uint32_t addr) {
    asm volatile("ldmatrix.sync.aligned.m8n8.x4.shared.b16 {%0,%1,%2,%3}, [%4];"
                 : "=r"(r[0]), "=r"(r[1]), "=r"(r[2]), "=r"(r[3]) : "r"(addr));
}

__device__ __forceinline__ void mma_f16(
    float* c, uint32_t a0, uint32_t a1, uint32_t a2, uint32_t a3,
    uint32_t b0, uint32_t b1)
{
    asm volatile(
        "mma.sync.aligned.m16n8k16.row.col.f32.f16.f16.f32 "
        "{%0,%1,%2,%3}, {%4,%5,%6,%7}, {%8,%9}, {%0,%1,%2,%3};"
        : "+f"(c[0]), "+f"(c[1]), "+f"(c[2]), "+f"(c[3])
        : "r"(a0), "r"(a1), "r"(a2), "r"(a3), "r"(b0), "r"(b1));
}

__device__ __forceinline__ uint32_t smem_to_u32(const void* p) {
    uint32_t a;
    asm("{ .reg .u64 t; cvta.to.shared.u64 t, %1; cvt.u32.u64 %0, t; }" : "=r"(a) : "l"(p));
    return a;
}

__global__ __launch_bounds__(256, 2) void gemm_h3(
    const __half* __restrict__ A, int lda,
    const __half* __restrict__ B,          // [N, Kd] K-major
    float* __restrict__ C,                 // fp32 out (nullable)
    int M, int N, int Kd,
    int mode, const float* __restrict__ aux,
    __half* __restrict__ Ch)               // fp16 out (nullable)
{
    extern __shared__ char smem[];
    const uint32_t smem_u = smem_to_u32(smem);
    const int tid  = threadIdx.x;
    const int lane = tid & 31;
    const int wid  = tid >> 5;             // 0..7
    const int wm   = wid >> 2;             // 0..1 (64-row half)
    const int wn   = wid & 3;              // 0..3 (32-col quarter)
    const int g    = lane >> 2;
    const int t4   = lane & 3;
    const int bm   = blockIdx.y * 128;
    const int bn   = blockIdx.x * 128;
    const int KT   = Kd >> 5;

    // copy slots: A 512 chunks + B 512 chunks, 4 per thread
    const int rA0 = tid >> 1,            cA0 = (tid & 1) * 2;       // 2 chunks A
    const int rB0 = tid >> 1,            cB0 = (tid & 1) * 2;       // 2 chunks B
    // (each thread copies A row rA0 cols cA0,cA0+1 and B row rB0 cols cB0,cB0+1)

    // ldmatrix lane offsets (bytes)
    const uint32_t a_lo = (uint32_t)(((lane & 15) * STR + ((lane >> 4) << 3)) * 2);
    const uint32_t b_lo = (uint32_t)((((lane & 7) + ((lane >> 4) << 3)) * STR
                                      + (((lane >> 3) & 1) << 3)) * 2);
    const uint32_t a_warp = (uint32_t)((wm * 64) * STR * 2);
    const uint32_t b_warp = (uint32_t)((wn * 32) * STR * 2);

    auto issue_tile = [&](int kt) {
        const uint32_t sb = smem_u + (kt % NSTAGE) * STAGE_BYTES;
        const int kbase = kt << 5;
        #pragma unroll
        for (int j = 0; j < 2; ++j) {
            const int c = cA0 + j;
            const uint32_t off = (uint32_t)((rA0 * STR + c * 8) * 2);
            cpa16(sb + off, A + (size_t)(bm + rA0) * lda + kbase + c * 8, true);
            cpa16(sb + TILE_BYTES + off,
                  B + (size_t)(bn + rB0) * Kd + kbase + c * 8, bn + rB0 < N);
        }
    };

    issue_tile(0); CP_COMMIT();
    if (KT > 1) { issue_tile(1); CP_COMMIT(); } else { CP_COMMIT(); }

    float acc[4][4][4];
    #pragma unroll
    for (int m = 0; m < 4; ++m)
        #pragma unroll
        for (int n = 0; n < 4; ++n)
            #pragma unroll
            for (int j = 0; j < 4; ++j) acc[m][n][j] = 0.f;

    for (int kt = 0; kt < KT; ++kt) {
        if (kt + 2 < KT) issue_tile(kt + 2);
        CP_COMMIT();
        CP_WAIT2();
        __syncthreads();

        const uint32_t sb = smem_u + (kt % NSTAGE) * STAGE_BYTES;
        const uint32_t ab = sb + a_warp + a_lo;
        const uint32_t bb = sb + TILE_BYTES + b_warp + b_lo;
        #pragma unroll
        for (int ks = 0; ks < 2; ++ks) {
            uint32_t a[4][4];
            #pragma unroll
            for (int m = 0; m < 4; ++m)
                ldm_x4(a[m], ab + (uint32_t)(m * 16 * STR * 2) + ks * 32);
            uint32_t b[2][4];
            #pragma unroll
            for (int j = 0; j < 2; ++j)
                ldm_x4(b[j], bb + (uint32_t)(j * 16 * STR * 2) + ks * 32);
            #pragma unroll
            for (int m = 0; m < 4; ++m) {
                mma_f16(acc[m][0], a[m][0], a[m][1], a[m][2], a[m][3], b[0][0], b[0][1]);
                mma_f16(acc[m][1], a[m][0], a[m][1], a[m][2], a[m][3], b[0][2], b[0][3]);
                mma_f16(acc[m][2], a[m][0], a[m][1], a[m][2], a[m][3], b[1][0], b[1][1]);
                mma_f16(acc[m][3], a[m][0], a[m][1], a[m][2], a[m][3], b[1][2], b[1][3]);
            }
        }
        __syncthreads();
    }

    // ---- epilogue ----
    #pragma unroll
    for (int m = 0; m < 4; ++m) {
        const int row0 = bm + wm * 64 + m * 16 + g;
        const size_t r0 = (size_t)row0 * N;
        const size_t r1 = (size_t)(row0 + 8) * N;
        #pragma unroll
        for (int n = 0; n < 4; ++n) {
            const int col = bn + wn * 32 + n * 8 + 2 * t4;
            if (col < N) {
                float v0 = acc[m][n][0], v1 = acc[m][n][1];
                float v2 = acc[m][n][2], v3 = acc[m][n][3];
                if (mode == 1) {
                    const float b0 = aux[col], b1 = aux[col + 1];
                    v0 += b0; v1 += b1; v2 += b0; v3 += b1;
                    v0 = fmaxf(v0, 0.f) + log1pf(__expf(-fabsf(v0)));
                    v1 = fmaxf(v1, 0.f) + log1pf(__expf(-fabsf(v1)));
                    v2 = fmaxf(v2, 0.f) + log1pf(__expf(-fabsf(v2)));
                    v3 = fmaxf(v3, 0.f) + log1pf(__expf(-fabsf(v3)));
                } else if (mode == 2) {
                    const float2 x0 = *(const float2*)(aux + r0 + col);
                    const float2 x1 = *(const float2*)(aux + r1 + col);
                    v0 += x0.x; v1 += x0.y; v2 += x1.x; v3 += x1.y;
                }
                if (C) {
                    *(float2*)(C + r0 + col) = make_float2(v0, v1);
                    *(float2*)(C + r1 + col) = make_float2(v2, v3);
                }
                if (Ch) {
                    *(__half2*)(Ch + r0 + col) = __floats2half2_rn(v0, v1);
                    *(__half2*)(Ch + r1 + col) = __floats2half2_rn(v2, v3);
                }
            }
        }
    }
}

// ---------------- RMSNorm (stores fp16 h) ------------------------------------
__global__ __launch_bounds__(256) void rmsnorm_kernel(
    const float* __restrict__ x, const float* __restrict__ nw,
    __half* __restrict__ h)
{
    __shared__ float red[8];
    __shared__ float s_scale;
    const int row = blockIdx.x;
    const int t = threadIdx.x;
    const float4 v = ((const float4*)(x + (size_t)row * DM))[t];
    float ss = v.x*v.x + v.y*v.y + v.z*v.z + v.w*v.w;
    #pragma unroll
    for (int o = 16; o > 0; o >>= 1) ss += __shfl_down_sync(0xffffffffu, ss, o);
    if ((t & 31) == 0) red[t >> 5] = ss;
    __syncthreads();
    if (t == 0) {
        float tot = 0.f;
        #pragma unroll
        for (int i = 0; i < 8; i++) tot += red[i];
        s_scale = rsqrtf(tot * (1.0f / DM) + 1e-5f);
    }
    __syncthreads();
    const float sc = s_scale;
    const float4 w = ((const float4*)nw)[t];
    ((__half2*)(h + (size_t)row * DM))[t * 2] =
        __floats2half2_rn(v.x * sc * w.x, v.y * sc * w.y);
    ((__half2*)(h + (size_t)row * DM))[t * 2 + 1] =
        __floats2half2_rn(v.z * sc * w.z, v.w * sc * w.w);
}

// ---------------- depthwise causal conv + bias + SiLU ------------------------
__global__ __launch_bounds__(256) void conv_silu_kernel(
    const __half* __restrict__ xz, const float* __restrict__ w,
    const float* __restrict__ bias, float* __restrict__ u,
    __half* __restrict__ uh)
{
    const long long idx = (long long)blockIdx.x * blockDim.x + threadIdx.x;
    if (idx >= (long long)MROWS * EDIM) return;
    const int e  = (int)(idx & (EDIM - 1));
    const int ml = (int)(idx >> 11);
    const int l  = ml & (SEQL - 1);
    float acc = bias[e];
    const float4 wv = *(const float4*)(w + e * 4);
    const float wk[4] = {wv.x, wv.y, wv.z, wv.w};
    #pragma unroll
    for (int k = 0; k < 4; k++) {
        const int ls = l - 3 + k;
        if (ls >= 0)
            acc = fmaf(__half2float(xz[(size_t)(ml - 3 + k) * E2 + e]), wk[k], acc);
    }
    const float s = 1.f / (1.f + __expf(-acc));
    const float uv = acc * s;
    u[(size_t)ml * EDIM + e]  = uv;
    uh[(size_t)ml * EDIM + e] = __float2half_rn(uv);
}

// ---------------- selective scan (prefetched, stores fp16 y) ------------------
__global__ __launch_bounds__(256) void scan_kernel(
    const float* __restrict__ delta, const float* __restrict__ u,
    const float* __restrict__ dbc,   const __half* __restrict__ xz,
    const float* __restrict__ A_log, const float* __restrict__ D_skip,
    __half* __restrict__ y)
{
    const int gg = blockIdx.x * blockDim.x + threadIdx.x;
    const int chain = gg >> 2;
    const int tq = gg & 3;
    const int b = chain >> 11;
    const int e = chain & (EDIM - 1);

    float Av[4];
    #pragma unroll
    for (int i = 0; i < 4; i++)
        Av[i] = -__expf(A_log[e * NST + tq * 4 + i]);
    const float Dv = D_skip[e];

    float hs0 = 0.f, hs1 = 0.f, hs2 = 0.f, hs3 = 0.f;
    const size_t base = (size_t)b * SEQL;

    // prefetch step 0
    size_t r = base;
    float  d_c  = delta[r * EDIM + e];
    float  u_c  = u[r * EDIM + e];
    float  z_c  = __half2float(xz[r * E2 + EDIM + e]);
    float4 B_c  = *(const float4*)(dbc + r * FDIM + RDIM + tq * 4);
    float4 C_c  = *(const float4*)(dbc + r * FDIM + RDIM + NST + tq * 4);

    for (int l = 0; l < SEQL; ++l) {
        float d_n = 0.f, u_n = 0.f, z_n = 0.f;
        float4 B_n = make_float4(0,0,0,0), C_n = make_float4(0,0,0,0);
        if (l + 1 < SEQL) {
            const size_t rn = base + l + 1;
            d_n = delta[rn * EDIM + e];
            u_n = u[rn * EDIM + e];
            z_n = __half2float(xz[rn * E2 + EDIM + e]);
            B_n = *(const float4*)(dbc + rn * FDIM + RDIM + tq * 4);
            C_n = *(const float4*)(dbc + rn * FDIM + RDIM + NST + tq * 4);
        }

        const float du = d_c * u_c;
        hs0 = fmaf(hs0, __expf(d_c * Av[0]), du * B_c.x);
        hs1 = fmaf(hs1, __expf(d_c * Av[1]), du * B_c.y);
        hs2 = fmaf(hs2, __expf(d_c * Av[2]), du * B_c.z);
        hs3 = fmaf(hs3, __expf(d_c * Av[3]), du * B_c.w);

        float yp = hs0 * C_c.x + hs1 * C_c.y + hs2 * C_c.z + hs3 * C_c.w;
        yp += __shfl_xor_sync(0xffffffffu, yp, 1);
        yp += __shfl_xor_sync(0xffffffffu, yp, 2);

        if (tq == 0) {
            const float sg = 1.f / (1.f + __expf(-z_c));
            y[(base + l) * EDIM + e] = __float2half_rn((yp + u_c * Dv) * (z_c * sg));
        }
        d_c = d_n; u_c = u_n; z_c = z_n; B_c = B_n; C_c = C_n;
    }
}

// ---------------- launch ------------------------------------------------------
extern "C" void kernel_launch(void* const* d_in, const int* in_sizes, int n_in,
                              void* d_out, int out_size)
{
    const float* x          = (const float*)d_in[0];
    const float* norm_w     = (const float*)d_in[1];
    const float* in_proj_w  = (const float*)d_in[2];
    const float* conv_w     = (const float*)d_in[3];
    const float* conv_b     = (const float*)d_in[4];
    const float* x_proj_w   = (const float*)d_in[5];
    const float* dt_proj_w  = (const float*)d_in[6];
    const float* dt_proj_b  = (const float*)d_in[7];
    const float* A_log      = (const float*)d_in[8];
    const float* D_skip     = (const float*)d_in[9];
    const float* out_proj_w = (const float*)d_in[10];
    float* out = (float*)d_out;

    float *pu, *pdbc, *pdelta;
    __half *pxz_h, *ph_h, *pu_h, *pdbc_h, *py_h;
    __half *pw_in, *pw_x, *pw_dt, *pw_out;
    cudaGetSymbolAddress((void**)&pxz_h,  g_xz_h);
    cudaGetSymbolAddress((void**)&pu,     g_u);
    cudaGetSymbolAddress((void**)&pdbc,   g_dbc);
    cudaGetSymbolAddress((void**)&pdelta, g_delta);
    cudaGetSymbolAddress((void**)&ph_h,   g_h_h);
    cudaGetSymbolAddress((void**)&pu_h,   g_u_h);
    cudaGetSymbolAddress((void**)&pdbc_h, g_dbc_h);
    cudaGetSymbolAddress((void**)&py_h,   g_y_h);
    cudaGetSymbolAddress((void**)&pw_in,  g_w_in);
    cudaGetSymbolAddress((void**)&pw_x,   g_w_x);
    cudaGetSymbolAddress((void**)&pw_dt,  g_w_dt);
    cudaGetSymbolAddress((void**)&pw_out, g_w_out);

    cudaFuncSetAttribute(gemm_h3, cudaFuncAttributeMaxDynamicSharedMemorySize,
                         GEMM_SMEM_BYTES);

    // 0. convert weights to fp16
    {
        const int n_in4  = E2 * DM / 4;
        const int n_x4   = FDIM * EDIM / 4;
        const int n_dt4  = EDIM * RDIM / 4;
        const int n_out4 = DM * EDIM / 4;
        conv_f16_k<<<(n_in4 + 255) / 256, 256>>>(in_proj_w, pw_in, n_in4);
        conv_f16_k<<<(n_x4 + 255) / 256, 256>>>(x_proj_w, pw_x, n_x4);
        conv_f16_k<<<(n_dt4 + 255) / 256, 256>>>(dt_proj_w, pw_dt, n_dt4);
        conv_f16_k<<<(n_out4 + 255) / 256, 256>>>(out_proj_w, pw_out, n_out4);
    }

    // 1. RMSNorm -> h (fp16)
    rmsnorm_kernel<<<MROWS, 256>>>(x, norm_w, ph_h);

    // 2. xz = h @ in_proj_w^T   [16384, 4096] -> fp16 only
    {
        dim3 grid(E2 / 128, MROWS / 128);
        gemm_h3<<<grid, 256, GEMM_SMEM_BYTES>>>(ph_h, DM, pw_in, nullptr,
                                                MROWS, E2, DM, 0, nullptr, pxz_h);
    }

    // 3. depthwise conv + SiLU -> u (fp32 + fp16)
    {
        long long tot = (long long)MROWS * EDIM;
        conv_silu_kernel<<<(unsigned)((tot + 255) / 256), 256>>>(pxz_h, conv_w, conv_b,
                                                                 pu, pu_h);
    }

    // 4. dbc = u @ x_proj_w^T  [16384, 96] (fp32 + fp16)
    {
        dim3 grid(1, MROWS / 128);
        gemm_h3<<<grid, 256, GEMM_SMEM_BYTES>>>(pu_h, EDIM, pw_x, pdbc,
                                                MROWS, FDIM, EDIM, 0, nullptr, pdbc_h);
    }

    // 5. delta = softplus(dbc[:, :64] @ dt_proj_w^T + b)  [16384, 2048] fp32
    {
        dim3 grid(EDIM / 128, MROWS / 128);
        gemm_h3<<<grid, 256, GEMM_SMEM_BYTES>>>(pdbc_h, FDIM, pw_dt, pdelta,
                                                MROWS, EDIM, RDIM, 1, dt_proj_b, nullptr);
    }

    // 6. selective scan -> y (fp16)
    scan_kernel<<<(MROWS * 4) / 256, 256>>>(pdelta, pu, pdbc, pxz_h, A_log, D_skip, py_h);

    // 7. out = y @ out_proj_w^T + x   [16384, 1024] fp32
    {
        dim3 grid(DM / 128, MROWS / 128);
        gemm_h3<<<grid, 256, GEMM_SMEM_BYTES>>>(py_h, EDIM, pw_out, out,
                                                MROWS, DM, EDIM, 2, x, nullptr);
    }
}